// round 11
// baseline (speedup 1.0000x reference)
#include <cuda_runtime.h>
#include <cuda_fp16.h>
#include <cstdint>
#include <math.h>

// ---------------- Problem constants ----------------
#define VOCAB 32000
#define DMODEL 1024
#define DEPTH 6
#define NHEAD 16
#define SEQL 1024
#define BATCH 2
#define LRANK 16
#define HIDDEN 4096
#define HEADDIM 64
#define NTOK (BATCH * SEQL)          // 2048
#define SCALING 0.5f                  // 8.0 / 16

// ---------------- Scratch (device globals; no allocation allowed) -------------
static __device__ float  g_x  [NTOK * DMODEL];
static __device__ __half g_h  [NTOK * DMODEL];
static __device__ __half g_qkv[NTOK * 3 * DMODEL];
static __device__ __half g_o  [NTOK * DMODEL];
static __device__ __half g_ff [NTOK * HIDDEN];
static __device__ __half g_wqkv[DEPTH * 3 * DMODEL * DMODEL];
static __device__ float  g_bqkv[DEPTH * 3 * DMODEL];
static __device__ __half g_wo  [DEPTH * DMODEL * DMODEL];
static __device__ __half g_w1c [DEPTH * HIDDEN * DMODEL];
static __device__ __half g_w2c [DEPTH * DMODEL * HIDDEN];
static __device__ __half g_headc[(long)VOCAB * DMODEL];

// ---------------- small PTX helpers (baseline ISA only) ----------------
__device__ __forceinline__ uint32_t smem_u32(const void* p) {
    uint32_t a;
    asm("{ .reg .u64 t; cvta.to.shared.u64 t, %1; cvt.u32.u64 %0, t; }"
        : "=r"(a) : "l"(p));
    return a;
}
__device__ __forceinline__ void cp16(uint32_t dst, const void* src) {
    asm volatile("cp.async.cg.shared.global [%0], [%1], 16;"
                 :: "r"(dst), "l"(src));
}
#define CP_COMMIT() asm volatile("cp.async.commit_group;" ::: "memory")
#define CP_WAIT1()  asm volatile("cp.async.wait_group 1;"  ::: "memory")
#define CP_WAIT0()  asm volatile("cp.async.wait_group 0;"  ::: "memory")

// fp16 MMA: m16n8k16, fp32 accumulate
__device__ __forceinline__ void mma_f16(float* d, const uint32_t* a,
                                        const uint32_t* b) {
    asm volatile(
        "mma.sync.aligned.m16n8k16.row.col.f32.f16.f16.f32 "
        "{%0,%1,%2,%3}, {%4,%5,%6,%7}, {%8,%9}, {%0,%1,%2,%3};"
        : "+f"(d[0]), "+f"(d[1]), "+f"(d[2]), "+f"(d[3])
        : "r"(a[0]), "r"(a[1]), "r"(a[2]), "r"(a[3]), "r"(b[0]), "r"(b[1]));
}

// ldmatrix x4: loads 4 8x8 fp16 matrices; per-thread address = one 16B row
__device__ __forceinline__ void ldsm_x4(uint32_t* r, uint32_t addr) {
    asm volatile("ldmatrix.sync.aligned.m8n8.x4.shared.b16 {%0,%1,%2,%3}, [%4];"
                 : "=r"(r[0]), "=r"(r[1]), "=r"(r[2]), "=r"(r[3])
                 : "r"(addr));
}

// ---------------- helpers ----------------
__device__ __forceinline__ float gelu_exact(float x) {
    return 0.5f * x * (1.0f + erff(x * 0.70710678118654752440f));
}
__device__ __forceinline__ uint32_t pack_h2(float a, float b) {
    __half2 h = __floats2half2_rn(a, b);
    return *reinterpret_cast<uint32_t*>(&h);
}

// ---------------- fp16 round-copy (for W1/W2/headW) ----------------
__global__ void conv_f16_kernel(const float* __restrict__ src,
                                __half* __restrict__ dst) {
    long e4 = ((long)blockIdx.x * 256 + threadIdx.x) * 4;
    float4 f = *reinterpret_cast<const float4*>(src + e4);
    uint2 u;
    u.x = pack_h2(f.x, f.y);
    u.y = pack_h2(f.z, f.w);
    *reinterpret_cast<uint2*>(dst + e4) = u;
}

// ---------------- LoRA fold body (writes fp16) ----------------
__device__ __forceinline__ void weff_body(long e4,
                                          const float* __restrict__ W,
                                          const float* __restrict__ Am,
                                          const float* __restrict__ Bm,
                                          __half* __restrict__ out,
                                          long outLS, long outOff) {
    const int DD4 = DMODEL * DMODEL / 4;
    int layer = (int)(e4 / DD4);
    int rem4  = (int)(e4 % DD4);
    int orow  = rem4 / (DMODEL / 4);
    int ic4   = (rem4 % (DMODEL / 4)) * 4;
    const float* a  = Am + (long)layer * DMODEL * LRANK + (long)orow * LRANK;
    const float* bb = Bm + (long)layer * LRANK * DMODEL + ic4;
    float4 s = make_float4(0.f, 0.f, 0.f, 0.f);
#pragma unroll
    for (int r = 0; r < LRANK; r++) {
        float4 bv = *reinterpret_cast<const float4*>(bb + (long)r * DMODEL);
        float av = a[r];
        s.x += av * bv.x; s.y += av * bv.y; s.z += av * bv.z; s.w += av * bv.w;
    }
    float4 wv = *reinterpret_cast<const float4*>(
        W + (long)layer * DMODEL * DMODEL + rem4 * 4);
    uint2 u;
    u.x = pack_h2(wv.x + SCALING * s.x, wv.y + SCALING * s.y);
    u.y = pack_h2(wv.z + SCALING * s.z, wv.w + SCALING * s.w);
    *reinterpret_cast<uint2*>(out + (long)layer * outLS + outOff + rem4 * 4) = u;
}

__global__ void weff_qkv_kernel(const float* __restrict__ Wq, const float* __restrict__ Aq, const float* __restrict__ Bq,
                                const float* __restrict__ Wk, const float* __restrict__ Ak, const float* __restrict__ Bk,
                                const float* __restrict__ Wv, const float* __restrict__ Av, const float* __restrict__ Bv,
                                __half* __restrict__ out) {
    const int nblk = DEPTH * DMODEL * DMODEL / 4 / 256;
    int seg = blockIdx.x / nblk;
    long e4 = (long)(blockIdx.x % nblk) * 256 + threadIdx.x;
    const long DD = (long)DMODEL * DMODEL;
    const float *W = (seg == 0) ? Wq : (seg == 1 ? Wk : Wv);
    const float *A = (seg == 0) ? Aq : (seg == 1 ? Ak : Av);
    const float *B = (seg == 0) ? Bq : (seg == 1 ? Bk : Bv);
    weff_body(e4, W, A, B, out, 3 * DD, seg * DD);
}

__global__ void weff_kernel(const float* __restrict__ W,
                            const float* __restrict__ Am,
                            const float* __restrict__ Bm,
                            __half* __restrict__ out,
                            long outLS, long outOff) {
    long e4 = (long)blockIdx.x * 256 + threadIdx.x;
    weff_body(e4, W, Am, Bm, out, outLS, outOff);
}

// ---------------- bias concat for fused QKV ----------------
__global__ void bias_concat_kernel(const float* __restrict__ bq,
                                   const float* __restrict__ bk,
                                   const float* __restrict__ bv,
                                   float* __restrict__ out) {
    int e = blockIdx.x * 256 + threadIdx.x;
    int layer = e / (3 * DMODEL);
    int r = e % (3 * DMODEL);
    const float* src = (r < DMODEL) ? bq : (r < 2 * DMODEL ? bk : bv);
    out[e] = src[layer * DMODEL + (r % DMODEL)];
}

// ---------------- Embedding + phase rotator (x stays fp32) ----------------
__global__ void embed_kernel(const int* __restrict__ idx,
                             const float* __restrict__ tok,
                             const float* __restrict__ pos,
                             const float* __restrict__ phase,
                             float* __restrict__ x) {
    int row = blockIdx.x;
    int l   = row % SEQL;
    int t   = idx[row];
    for (int d = threadIdx.x; d < DMODEL; d += blockDim.x) {
        float phi = tanhf(phase[d]) * 3.14159265358979323846f;
        float fac = cosf(phi) - sinf(phi);
        x[(long)row * DMODEL + d] =
            (tok[(long)t * DMODEL + d] + pos[(long)l * DMODEL + d]) * fac;
    }
}

// ---------------- LayerNorm (fp32 in, fp16 out) ----------------
__global__ void ln_kernel(const float* __restrict__ x,
                          const float* __restrict__ w,
                          const float* __restrict__ b,
                          __half* __restrict__ o) {
    int row = blockIdx.x;
    const float* xr = x + (long)row * DMODEL;
    int tid = threadIdx.x;
    float s = 0.f, s2 = 0.f;
    float v[4];
#pragma unroll
    for (int j = 0; j < 4; j++) {
        v[j] = xr[tid + 256 * j];
        s += v[j]; s2 += v[j] * v[j];
    }
    __shared__ float r1[256], r2[256];
    r1[tid] = s; r2[tid] = s2;
    __syncthreads();
    for (int off = 128; off > 0; off >>= 1) {
        if (tid < off) { r1[tid] += r1[tid + off]; r2[tid] += r2[tid + off]; }
        __syncthreads();
    }
    float mean = r1[0] * (1.0f / DMODEL);
    float var  = r2[0] * (1.0f / DMODEL) - mean * mean;
    float rstd = rsqrtf(var + 1e-5f);
    __half* orow = o + (long)row * DMODEL;
#pragma unroll
    for (int j = 0; j < 4; j++) {
        int d = tid + 256 * j;
        orow[d] = __float2half_rn((v[j] - mean) * rstd * w[d] + b[d]);
    }
}

// ---------------- Fused flash attention (fp16 MMA + ldmatrix) ---------------
// grid: (8 q-tiles, 32 batch-heads), 256 threads (8 warps x 16 q-rows).
static constexpr int FA_K_OFF  = 0;
static constexpr int FA_V_OFF  = 128 * 72;
static constexpr int FA_VT_OFF = 2 * 128 * 72;
static constexpr int FA_P_OFF  = 2 * 128 * 72 + 64 * 136;
static constexpr int FA_HALVES = FA_P_OFF + 128 * 136;
static constexpr int FA_SMEM   = FA_HALVES * 2;                   // 89088 B

__global__ __launch_bounds__(256)
void flash_attn_kernel(const __half* __restrict__ qkv, __half* __restrict__ o) {
    extern __shared__ __half fh[];
    __half* Kt   = fh + FA_K_OFF;
    __half* Vraw = fh + FA_V_OFF;
    __half* VtT  = fh + FA_VT_OFF;
    __half* Pu   = fh + FA_P_OFF;
    __half* Qs   = Pu;                     // Q staging reuses P region

    const int qt = blockIdx.x;
    const int bh = blockIdx.y;
    const int b  = bh >> 4;
    const int h  = bh & 15;

    const int tid  = threadIdx.x;
    const int wid  = tid >> 5;
    const int lane = tid & 31;
    const int g = lane >> 2, tig = lane & 3;

    const int lrow  = lane & 7;
    const int a_row = ((lane >> 3) & 1) * 8;
    const int a_k   = (lane >> 4) * 8;
    const int b_row = (lane >> 4) * 8;
    const int b_k   = ((lane >> 3) & 1) * 8;

    const __half* base = qkv + ((long)b * SEQL) * (3 * DMODEL) + h * HEADDIM;

    // ---- stage Q tile
    {
        int r = tid >> 1, hp = tid & 1;
        const __half* src = base + (long)(qt * 128 + r) * (3 * DMODEL) + hp * 32;
        uint32_t dst = smem_u32(&Qs[r * 72 + hp * 32]);
#pragma unroll
        for (int i = 0; i < 4; i++) cp16(dst + i * 16, src + i * 8);
    }
    CP_COMMIT(); CP_WAIT0(); __syncthreads();

    const __half2 qscale = __floats2half2_rn(0.125f, 0.125f);
    uint32_t qf[4][4];
    {
        uint32_t qbase = smem_u32(Qs) +
            ((wid * 16 + a_row + lrow) * 72 + a_k) * 2;
#pragma unroll
        for (int ks = 0; ks < 4; ks++) {
            uint32_t r[4];
            ldsm_x4(r, qbase + ks * 32);
#pragma unroll
            for (int z = 0; z < 4; z++) {
                __half2 hv = __hmul2(*(__half2*)&r[z], qscale);
                qf[ks][z] = *(uint32_t*)&hv;
            }
        }
    }
    __syncthreads();

    float mold0 = -INFINITY, mold1 = -INFINITY;
    float l0 = 0.f, l1 = 0.f;
    float oacc[8][4];
#pragma unroll
    for (int n = 0; n < 8; n++)
#pragma unroll
        for (int r = 0; r < 4; r++) oacc[n][r] = 0.f;

    const uint32_t kt_b_base  = smem_u32(Kt)  + ((b_row + lrow) * 72 + b_k) * 2;
    const uint32_t vt_b_base  = smem_u32(VtT) + ((b_row + lrow) * 136 + b_k) * 2;
    const uint32_t pu_a_base  = smem_u32(Pu) +
        ((wid * 16 + a_row + lrow) * 136 + a_k) * 2;

    for (int kt = 0; kt <= qt; kt++) {
        {
            int r = tid >> 1, hp = tid & 1;
            const __half* ksrc = base + (long)(kt * 128 + r) * (3 * DMODEL) + DMODEL + hp * 32;
            const __half* vsrc = base + (long)(kt * 128 + r) * (3 * DMODEL) + 2 * DMODEL + hp * 32;
            uint32_t kd = smem_u32(&Kt[r * 72 + hp * 32]);
            uint32_t vd = smem_u32(&Vraw[r * 72 + hp * 32]);
#pragma unroll
            for (int i = 0; i < 4; i++) cp16(kd + i * 16, ksrc + i * 8);
#pragma unroll
            for (int i = 0; i < 4; i++) cp16(vd + i * 16, vsrc + i * 8);
        }
        CP_COMMIT(); CP_WAIT0(); __syncthreads();

        {
            int r = tid >> 1, hp = tid & 1;
            const __half* vr = &Vraw[r * 72 + hp * 32];
#pragma unroll
            for (int j = 0; j < 32; j++)
                VtT[(hp * 32 + j) * 136 + r] = vr[j];
        }
        __syncthreads();

        float sacc[16][4];
#pragma unroll
        for (int n = 0; n < 16; n++)
#pragma unroll
            for (int r = 0; r < 4; r++) sacc[n][r] = 0.f;
#pragma unroll
        for (int ntp = 0; ntp < 8; ntp++) {
            uint32_t baddr = kt_b_base + ntp * (16 * 72 * 2);
#pragma unroll
            for (int ks = 0; ks < 4; ks++) {
                uint32_t r[4];
                ldsm_x4(r, baddr + ks * 32);
                mma_f16(sacc[2 * ntp    ], qf[ks], r);
                mma_f16(sacc[2 * ntp + 1], qf[ks], r + 2);
            }
        }

        if (kt == qt) {
            int r0 = wid * 16 + g, r1 = r0 + 8;
#pragma unroll
            for (int nt = 0; nt < 16; nt++) {
                int c0 = nt * 8 + tig * 2;
                if (c0     > r0) sacc[nt][0] = -INFINITY;
                if (c0 + 1 > r0) sacc[nt][1] = -INFINITY;
                if (c0     > r1) sacc[nt][2] = -INFINITY;
                if (c0 + 1 > r1) sacc[nt][3] = -INFINITY;
            }
        }

        float tm0 = -INFINITY, tm1 = -INFINITY;
#pragma unroll
        for (int nt = 0; nt < 16; nt++) {
            tm0 = fmaxf(tm0, fmaxf(sacc[nt][0], sacc[nt][1]));
            tm1 = fmaxf(tm1, fmaxf(sacc[nt][2], sacc[nt][3]));
        }
        tm0 = fmaxf(tm0, __shfl_xor_sync(0xffffffffu, tm0, 1));
        tm0 = fmaxf(tm0, __shfl_xor_sync(0xffffffffu, tm0, 2));
        tm1 = fmaxf(tm1, __shfl_xor_sync(0xffffffffu, tm1, 1));
        tm1 = fmaxf(tm1, __shfl_xor_sync(0xffffffffu, tm1, 2));
        float mn0 = fmaxf(mold0, tm0), mn1 = fmaxf(mold1, tm1);
        float a0 = __expf(mold0 - mn0), a1 = __expf(mold1 - mn1);

        float sum0 = 0.f, sum1 = 0.f;
        int prow = wid * 16 + g;
        uint32_t* Pw = (uint32_t*)Pu;
#pragma unroll
        for (int nt = 0; nt < 16; nt++) {
            float p0 = __expf(sacc[nt][0] - mn0);
            float p1 = __expf(sacc[nt][1] - mn0);
            float p2 = __expf(sacc[nt][2] - mn1);
            float p3 = __expf(sacc[nt][3] - mn1);
            sum0 += p0 + p1; sum1 += p2 + p3;
            int c = nt * 4 + tig;
            Pw[(prow    ) * 68 + c] = pack_h2(p0, p1);
            Pw[(prow + 8) * 68 + c] = pack_h2(p2, p3);
        }
        sum0 += __shfl_xor_sync(0xffffffffu, sum0, 1);
        sum0 += __shfl_xor_sync(0xffffffffu, sum0, 2);
        sum1 += __shfl_xor_sync(0xffffffffu, sum1, 1);
        sum1 += __shfl_xor_sync(0xffffffffu, sum1, 2);
        l0 = l0 * a0 + sum0;
        l1 = l1 * a1 + sum1;
#pragma unroll
        for (int nt = 0; nt < 8; nt++) {
            oacc[nt][0] *= a0; oacc[nt][1] *= a0;
            oacc[nt][2] *= a1; oacc[nt][3] *= a1;
        }
        mold0 = mn0; mold1 = mn1;
        __syncthreads();

#pragma unroll
        for (int ks = 0; ks < 8; ks++) {
            uint32_t af[4];
            ldsm_x4(af, pu_a_base + ks * 32);
#pragma unroll
            for (int ntp = 0; ntp < 4; ntp++) {
                uint32_t r[4];
                ldsm_x4(r, vt_b_base + ntp * (16 * 136 * 2) + ks * 32);
                mma_f16(oacc[2 * ntp    ], af, r);
                mma_f16(oacc[2 * ntp + 1], af, r + 2);
            }
        }
        __syncthreads();
    }

    float i0 = 1.0f / l0, i1 = 1.0f / l1;
    int tok = b * SEQL + qt * 128 + wid * 16 + g;
    __half* o0 = o + (long)tok * DMODEL + h * HEADDIM;
    __half* o1 = o0 + 8 * DMODEL;
#pragma unroll
    for (int nt = 0; nt < 8; nt++) {
        int c = nt * 8 + tig * 2;
        *(uint32_t*)&o0[c] = pack_h2(oacc[nt][0] * i0, oacc[nt][1] * i0);
        *(uint32_t*)&o1[c] = pack_h2(oacc[nt][2] * i1, oacc[nt][3] * i1);
    }
}

// ---------------- fp16 mma.sync GEMM (ldmatrix + 3-stage pipeline) ----------
// C[m,n] = sum_k A[m*lda+k] * B[n*sBn+k]  (+bias)(gelu); out fp32(+res) or fp16
// flags: 1 = gelu, 16 = grid swap, 32 = fp16 output
// BM=128 fixed; BN=128: 8 warps 2x4, warp tile 64x32.
//               BN=64 : 8 warps 4x2, warp tile 32x32 (high occupancy).
template<int BN>
__global__ __launch_bounds__(256)
void mma_gemm(const __half* __restrict__ A, int lda,
              const __half* __restrict__ Bp, long sBn,
              const float* __restrict__ bias,
              const float* __restrict__ res, int ldr,
              void* __restrict__ Cv, int ldc,
              int K, int flags) {
    constexpr int BM = 128, BK = 32, LDSH = BK + 8;   // 40 halves/row
    constexpr int STAGES = 3;
    constexpr int NW_N = BN / 32;          // warps along n
    constexpr int NW_M = 8 / NW_N;         // warps along m
    constexpr int WM_T = BM / (NW_M * 16); // m16 tiles per warp
    extern __shared__ __half smh[];
    __half* As = smh;                           // [STAGES][BM][40]
    __half* Bs = smh + STAGES * BM * LDSH;      // [STAGES][BN][40]

    int bx = blockIdx.x, by = blockIdx.y;
    if (flags & 16) { int t = bx; bx = by; by = t; }
    const int bm0 = by * BM;
    const int bn0 = bx * BN;
    const int T = K / BK;

    const int tid  = threadIdx.x;
    const int w    = tid >> 5;
    const int lane = tid & 31;
    const int wm = w / NW_N, wn = w % NW_N;
    const int g = lane >> 2, tig = lane & 3;

    const int lrow  = lane & 7;
    const int a_row = ((lane >> 3) & 1) * 8;
    const int a_k   = (lane >> 4) * 8;
    const int b_row = (lane >> 4) * 8;
    const int b_k   = ((lane >> 3) & 1) * 8;

    const uint32_t a_base = smem_u32(As) +
        ((wm * (WM_T * 16) + a_row + lrow) * LDSH + a_k) * 2;
    const uint32_t b_base = smem_u32(Bs) +
        ((wn * 32 + b_row + lrow) * LDSH + b_k) * 2;
    constexpr uint32_t ABUF = BM * LDSH * 2;
    constexpr uint32_t BBUF = BN * LDSH * 2;

    float acc[WM_T][4][4];
#pragma unroll
    for (int i = 0; i < WM_T; i++)
#pragma unroll
        for (int j = 0; j < 4; j++)
#pragma unroll
            for (int r = 0; r < 4; r++) acc[i][j][r] = 0.0f;

    auto load_tile = [&](int it, int buf) {
        const int k0 = it * BK;
#pragma unroll
        for (int t = 0; t < 2; t++) {               // A: 128 rows x 4 chunks
            int vv = tid + t * 256;
            int m = vv >> 2, c = vv & 3;
            cp16(smem_u32(&As[(buf * BM + m) * LDSH + c * 8]),
                 A + (long)(bm0 + m) * lda + k0 + c * 8);
        }
#pragma unroll
        for (int t = 0; t < BN / 64; t++) {         // B: BN rows x 4 chunks
            int vv = tid + t * 256;
            int n = vv >> 2, c = vv & 3;
            cp16(smem_u32(&Bs[(buf * BN + n) * LDSH + c * 8]),
                 Bp + (long)(bn0 + n) * sBn + k0 + c * 8);
        }
    };

    load_tile(0, 0);
    CP_COMMIT();
    if (T > 1) { load_tile(1, 1); CP_COMMIT(); }

    for (int it = 0; it < T; it++) {
        if (it + 1 < T) { CP_WAIT1(); } else { CP_WAIT0(); }
        __syncthreads();   // tile `it` visible to all; fences prior compute
        if (it + 2 < T) { load_tile(it + 2, (it + 2) % STAGES); CP_COMMIT(); }

        const int buf = it % STAGES;
        const uint32_t ab = a_base + buf * ABUF;
        const uint32_t bb = b_base + buf * BBUF;

#pragma unroll
        for (int ks = 0; ks < 2; ks++) {
            uint32_t af[WM_T][4];
#pragma unroll
            for (int i = 0; i < WM_T; i++)
                ldsm_x4(af[i], ab + i * (16 * LDSH * 2) + ks * 32);
            uint32_t bf[4][4];                  // 2 ldmatrix cover 4 n8 tiles
            ldsm_x4(bf[0], bb + ks * 32);
            ldsm_x4(bf[2], bb + 16 * LDSH * 2 + ks * 32);
#pragma unroll
            for (int i = 0; i < WM_T; i++) {
                mma_f16(acc[i][0], af[i], bf[0]);
                mma_f16(acc[i][1], af[i], bf[0] + 2);
                mma_f16(acc[i][2], af[i], bf[2]);
                mma_f16(acc[i][3], af[i], bf[2] + 2);
            }
        }
    }

    // epilogue -----------------------------------------------------------
#pragma unroll
    for (int i = 0; i < WM_T; i++) {
        int r0 = bm0 + wm * (WM_T * 16) + i * 16 + g;
#pragma unroll
        for (int j = 0; j < 4; j++) {
            int c = bn0 + wn * 32 + j * 8 + tig * 2;
            float e00 = acc[i][j][0], e01 = acc[i][j][1];
            float e10 = acc[i][j][2], e11 = acc[i][j][3];
            if (bias) {
                float2 bb2 = *reinterpret_cast<const float2*>(bias + c);
                e00 += bb2.x; e01 += bb2.y; e10 += bb2.x; e11 += bb2.y;
            }
            if (flags & 1) {
                e00 = gelu_exact(e00); e01 = gelu_exact(e01);
                e10 = gelu_exact(e10); e11 = gelu_exact(e11);
            }
            if (flags & 32) {
                __half* C = (__half*)Cv;
                *(uint32_t*)&C[(long)r0 * ldc + c]       = pack_h2(e00, e01);
                *(uint32_t*)&C[(long)(r0 + 8) * ldc + c] = pack_h2(e10, e11);
            } else {
                float* C = (float*)Cv;
                if (res) {
                    float2 ra = *reinterpret_cast<const float2*>(
                        res + (long)r0 * ldr + c);
                    float2 rb = *reinterpret_cast<const float2*>(
                        res + (long)(r0 + 8) * ldr + c);
                    e00 += ra.x; e01 += ra.y; e10 += rb.x; e11 += rb.y;
                }
                *reinterpret_cast<float2*>(C + (long)r0 * ldc + c) =
                    make_float2(e00, e01);
                *reinterpret_cast<float2*>(C + (long)(r0 + 8) * ldc + c) =
                    make_float2(e10, e11);
            }
        }
    }
}

// ---------------- host-side launch helpers ----------------
static constexpr int GEMM_SMEM128 = 3 * (128 * 40 + 128 * 40) * 2;  // 61440
static constexpr int GEMM_SMEM64  = 3 * (128 * 40 + 64 * 40) * 2;   // 46080

static void tgemm(const __half* A, int lda, const __half* B, long sBn,
                  const float* bias, const float* res, int ldr,
                  void* C, int ldc, int M, int N, int K, int flags) {
    dim3 gdim;
    if (flags & 16) gdim = dim3(M / 128, N / 128, 1);
    else            gdim = dim3(N / 128, M / 128, 1);
    mma_gemm<128><<<gdim, 256, GEMM_SMEM128>>>(A, lda, B, sBn, bias, res, ldr,
                                               C, ldc, K, flags);
}
static void tgemm64(const __half* A, int lda, const __half* B, long sBn,
                    const float* bias, const float* res, int ldr,
                    void* C, int ldc, int M, int N, int K, int flags) {
    dim3 gdim(N / 64, M / 128, 1);
    mma_gemm<64><<<gdim, 256, GEMM_SMEM64>>>(A, lda, B, sBn, bias, res, ldr,
                                             C, ldc, K, flags);
}

// ---------------- entry point ----------------
extern "C" void kernel_launch(void* const* d_in, const int* in_sizes, int n_in,
                              void* d_out, int out_size) {
    const int*   idx   = (const int*)  d_in[0];
    const float* tok   = (const float*)d_in[1];
    const float* pos   = (const float*)d_in[2];
    const float* phase = (const float*)d_in[3];
    const float* ln1w  = (const float*)d_in[4];
    const float* ln1b  = (const float*)d_in[5];

    const float *ln2w, *ln2b;
    int wbase;
    if (in_sizes[6] == DEPTH * DMODEL) {        // dict order
        ln2w = (const float*)d_in[6];
        ln2b = (const float*)d_in[7];
        wbase = 8;
    } else {                                     // signature order fallback
        ln2w = (const float*)d_in[22];
        ln2b = (const float*)d_in[23];
        wbase = 6;
    }
    const float* Wq = (const float*)d_in[wbase + 0];
    const float* bq = (const float*)d_in[wbase + 1];
    const float* Bq = (const float*)d_in[wbase + 2];
    const float* Aq = (const float*)d_in[wbase + 3];
    const float* Wk = (const float*)d_in[wbase + 4];
    const float* bk = (const float*)d_in[wbase + 5];
    const float* Bk = (const float*)d_in[wbase + 6];
    const float* Ak = (const float*)d_in[wbase + 7];
    const float* Wv = (const float*)d_in[wbase + 8];
    const float* bv = (const float*)d_in[wbase + 9];
    const float* Bv = (const float*)d_in[wbase + 10];
    const float* Av = (const float*)d_in[wbase + 11];
    const float* Wo = (const float*)d_in[wbase + 12];
    const float* bo = (const float*)d_in[wbase + 13];
    const float* Bo = (const float*)d_in[wbase + 14];
    const float* Ao = (const float*)d_in[wbase + 15];
    const float* W1 = (const float*)d_in[24];
    const float* b1 = (const float*)d_in[25];
    const float* W2 = (const float*)d_in[26];
    const float* b2 = (const float*)d_in[27];
    const float* lnfw = (const float*)d_in[28];
    const float* lnfb = (const float*)d_in[29];
    const float* headW = (const float*)d_in[30];
    float* out = (float*)d_out;

    float *x, *bqkv;
    __half *h, *qkv, *o, *ff, *wqkv, *wo, *w1c, *w2c, *headc;
    cudaGetSymbolAddress((void**)&x,    g_x);
    cudaGetSymbolAddress((void**)&h,    g_h);
    cudaGetSymbolAddress((void**)&qkv,  g_qkv);
    cudaGetSymbolAddress((void**)&o,    g_o);
    cudaGetSymbolAddress((void**)&ff,   g_ff);
    cudaGetSymbolAddress((void**)&wqkv, g_wqkv);
    cudaGetSymbolAddress((void**)&bqkv, g_bqkv);
    cudaGetSymbolAddress((void**)&wo,   g_wo);
    cudaGetSymbolAddress((void**)&w1c,  g_w1c);
    cudaGetSymbolAddress((void**)&w2c,  g_w2c);
    cudaGetSymbolAddress((void**)&headc, g_headc);

    cudaFuncSetAttribute(flash_attn_kernel,
                         cudaFuncAttributeMaxDynamicSharedMemorySize, FA_SMEM);
    cudaFuncSetAttribute(mma_gemm<128>,
                         cudaFuncAttributeMaxDynamicSharedMemorySize, GEMM_SMEM128);
    cudaFuncSetAttribute(mma_gemm<64>,
                         cudaFuncAttributeMaxDynamicSharedMemorySize, GEMM_SMEM64);

    const int D = DMODEL;
    const long DD = (long)D * D;

    // 1) weight prep: LoRA folds + fp16 conversions
    {
        int nblk = (int)(DEPTH * DD / 4 / 256);
        weff_qkv_kernel<<<3 * nblk, 256>>>(Wq, Aq, Bq, Wk, Ak, Bk, Wv, Av, Bv,
                                           wqkv);
        weff_kernel<<<nblk, 256>>>(Wo, Ao, Bo, wo, DD, 0);
        bias_concat_kernel<<<DEPTH * 3 * D / 256, 256>>>(bq, bk, bv, bqkv);
        conv_f16_kernel<<<DEPTH * HIDDEN * D / 1024, 256>>>(W1, w1c);
        conv_f16_kernel<<<DEPTH * HIDDEN * D / 1024, 256>>>(W2, w2c);
        conv_f16_kernel<<<VOCAB * D / 1024, 256>>>(headW, headc);
    }
    embed_kernel<<<NTOK, 256>>>(idx, tok, pos, phase, x);

    // 2) transformer layers
    for (int i = 0; i < DEPTH; i++) {
        const __half* wqkv_i = wqkv + (long)i * 3 * DD;
        const __half* woi    = wo + (long)i * DD;

        ln_kernel<<<NTOK, 256>>>(x, ln1w + i * D, ln1b + i * D, h);

        // fused QKV (fp16 output)
        tgemm(h, D, wqkv_i, D, bqkv + (long)i * 3 * D, nullptr, 0,
              qkv, 3 * D, NTOK, 3 * D, D, /*flags=*/32);

        flash_attn_kernel<<<dim3(SEQL / 128, BATCH * NHEAD), 256, FA_SMEM>>>(
            qkv, o);

        // x = x + o @ Wo_eff^T + bo  (BN=64: 256-CTA grid)
        tgemm64(o, D, woi, D, bo + i * D, x, D, x, D, NTOK, D, D, 0);

        ln_kernel<<<NTOK, 256>>>(x, ln2w + i * D, ln2b + i * D, h);

        // ff = fp16(gelu(h @ W1^T + b1))
        tgemm(h, D, w1c + (long)i * HIDDEN * D, D, b1 + i * HIDDEN,
              nullptr, 0, ff, HIDDEN, NTOK, HIDDEN, D, /*flags=*/1 | 32);
        // x = x + ff @ W2^T + b2  (BN=64: 256-CTA grid, K=4096 long loop)
        tgemm64(ff, HIDDEN, w2c + (long)i * D * HIDDEN, HIDDEN, b2 + i * D,
                x, D, x, D, NTOK, D, HIDDEN, 0);
    }

    // 3) final LN + LM head (grid-swapped for L2 B reuse)
    ln_kernel<<<NTOK, 256>>>(x, lnfw, lnfb, h);
    tgemm(h, D, headc, D, nullptr, nullptr, 0, out, VOCAB,
          NTOK, VOCAB, D, /*flags=*/16);
}

// round 12
// speedup vs baseline: 1.0137x; 1.0137x over previous
#include <cuda_runtime.h>
#include <cuda_fp16.h>
#include <cstdint>
#include <math.h>

// ---------------- Problem constants ----------------
#define VOCAB 32000
#define DMODEL 1024
#define DEPTH 6
#define NHEAD 16
#define SEQL 1024
#define BATCH 2
#define LRANK 16
#define HIDDEN 4096
#define HEADDIM 64
#define NTOK (BATCH * SEQL)          // 2048
#define SCALING 0.5f                  // 8.0 / 16

// ---------------- Scratch (device globals; no allocation allowed) -------------
static __device__ float  g_x  [NTOK * DMODEL];
static __device__ __half g_h  [NTOK * DMODEL];
static __device__ __half g_qkv[NTOK * 3 * DMODEL];
static __device__ __half g_o  [NTOK * DMODEL];
static __device__ __half g_ff [NTOK * HIDDEN];
static __device__ __half g_wqkv[DEPTH * 3 * DMODEL * DMODEL];
static __device__ float  g_bqkv[DEPTH * 3 * DMODEL];
static __device__ __half g_wo  [DEPTH * DMODEL * DMODEL];
static __device__ __half g_w1c [DEPTH * HIDDEN * DMODEL];
static __device__ __half g_w2c [DEPTH * DMODEL * HIDDEN];
static __device__ __half g_headc[(long)VOCAB * DMODEL];

// ---------------- small PTX helpers (baseline ISA only) ----------------
__device__ __forceinline__ uint32_t smem_u32(const void* p) {
    uint32_t a;
    asm("{ .reg .u64 t; cvta.to.shared.u64 t, %1; cvt.u32.u64 %0, t; }"
        : "=r"(a) : "l"(p));
    return a;
}
__device__ __forceinline__ void cp16(uint32_t dst, const void* src) {
    asm volatile("cp.async.cg.shared.global [%0], [%1], 16;"
                 :: "r"(dst), "l"(src));
}
#define CP_COMMIT() asm volatile("cp.async.commit_group;" ::: "memory")
#define CP_WAIT1()  asm volatile("cp.async.wait_group 1;"  ::: "memory")
#define CP_WAIT0()  asm volatile("cp.async.wait_group 0;"  ::: "memory")

// fp16 MMA: m16n8k16, fp32 accumulate
__device__ __forceinline__ void mma_f16(float* d, const uint32_t* a,
                                        const uint32_t* b) {
    asm volatile(
        "mma.sync.aligned.m16n8k16.row.col.f32.f16.f16.f32 "
        "{%0,%1,%2,%3}, {%4,%5,%6,%7}, {%8,%9}, {%0,%1,%2,%3};"
        : "+f"(d[0]), "+f"(d[1]), "+f"(d[2]), "+f"(d[3])
        : "r"(a[0]), "r"(a[1]), "r"(a[2]), "r"(a[3]), "r"(b[0]), "r"(b[1]));
}

// ldmatrix x4: loads 4 8x8 fp16 matrices; per-thread address = one 16B row
__device__ __forceinline__ void ldsm_x4(uint32_t* r, uint32_t addr) {
    asm volatile("ldmatrix.sync.aligned.m8n8.x4.shared.b16 {%0,%1,%2,%3}, [%4];"
                 : "=r"(r[0]), "=r"(r[1]), "=r"(r[2]), "=r"(r[3])
                 : "r"(addr));
}

// ---------------- helpers ----------------
__device__ __forceinline__ float gelu_exact(float x) {
    return 0.5f * x * (1.0f + erff(x * 0.70710678118654752440f));
}
__device__ __forceinline__ uint32_t pack_h2(float a, float b) {
    __half2 h = __floats2half2_rn(a, b);
    return *reinterpret_cast<uint32_t*>(&h);
}

// ---------------- fp16 round-copy (for W1/W2/headW) ----------------
__global__ void conv_f16_kernel(const float* __restrict__ src,
                                __half* __restrict__ dst) {
    long e4 = ((long)blockIdx.x * 256 + threadIdx.x) * 4;
    float4 f = *reinterpret_cast<const float4*>(src + e4);
    uint2 u;
    u.x = pack_h2(f.x, f.y);
    u.y = pack_h2(f.z, f.w);
    *reinterpret_cast<uint2*>(dst + e4) = u;
}

// ---------------- LoRA fold body (writes fp16) ----------------
__device__ __forceinline__ void weff_body(long e4,
                                          const float* __restrict__ W,
                                          const float* __restrict__ Am,
                                          const float* __restrict__ Bm,
                                          __half* __restrict__ out,
                                          long outLS, long outOff) {
    const int DD4 = DMODEL * DMODEL / 4;
    int layer = (int)(e4 / DD4);
    int rem4  = (int)(e4 % DD4);
    int orow  = rem4 / (DMODEL / 4);
    int ic4   = (rem4 % (DMODEL / 4)) * 4;
    const float* a  = Am + (long)layer * DMODEL * LRANK + (long)orow * LRANK;
    const float* bb = Bm + (long)layer * LRANK * DMODEL + ic4;
    float4 s = make_float4(0.f, 0.f, 0.f, 0.f);
#pragma unroll
    for (int r = 0; r < LRANK; r++) {
        float4 bv = *reinterpret_cast<const float4*>(bb + (long)r * DMODEL);
        float av = a[r];
        s.x += av * bv.x; s.y += av * bv.y; s.z += av * bv.z; s.w += av * bv.w;
    }
    float4 wv = *reinterpret_cast<const float4*>(
        W + (long)layer * DMODEL * DMODEL + rem4 * 4);
    uint2 u;
    u.x = pack_h2(wv.x + SCALING * s.x, wv.y + SCALING * s.y);
    u.y = pack_h2(wv.z + SCALING * s.z, wv.w + SCALING * s.w);
    *reinterpret_cast<uint2*>(out + (long)layer * outLS + outOff + rem4 * 4) = u;
}

__global__ void weff_qkv_kernel(const float* __restrict__ Wq, const float* __restrict__ Aq, const float* __restrict__ Bq,
                                const float* __restrict__ Wk, const float* __restrict__ Ak, const float* __restrict__ Bk,
                                const float* __restrict__ Wv, const float* __restrict__ Av, const float* __restrict__ Bv,
                                __half* __restrict__ out) {
    const int nblk = DEPTH * DMODEL * DMODEL / 4 / 256;
    int seg = blockIdx.x / nblk;
    long e4 = (long)(blockIdx.x % nblk) * 256 + threadIdx.x;
    const long DD = (long)DMODEL * DMODEL;
    const float *W = (seg == 0) ? Wq : (seg == 1 ? Wk : Wv);
    const float *A = (seg == 0) ? Aq : (seg == 1 ? Ak : Av);
    const float *B = (seg == 0) ? Bq : (seg == 1 ? Bk : Bv);
    weff_body(e4, W, A, B, out, 3 * DD, seg * DD);
}

__global__ void weff_kernel(const float* __restrict__ W,
                            const float* __restrict__ Am,
                            const float* __restrict__ Bm,
                            __half* __restrict__ out,
                            long outLS, long outOff) {
    long e4 = (long)blockIdx.x * 256 + threadIdx.x;
    weff_body(e4, W, Am, Bm, out, outLS, outOff);
}

// ---------------- bias concat for fused QKV ----------------
__global__ void bias_concat_kernel(const float* __restrict__ bq,
                                   const float* __restrict__ bk,
                                   const float* __restrict__ bv,
                                   float* __restrict__ out) {
    int e = blockIdx.x * 256 + threadIdx.x;
    int layer = e / (3 * DMODEL);
    int r = e % (3 * DMODEL);
    const float* src = (r < DMODEL) ? bq : (r < 2 * DMODEL ? bk : bv);
    out[e] = src[layer * DMODEL + (r % DMODEL)];
}

// ---------------- Embedding + phase rotator (x stays fp32) ----------------
__global__ void embed_kernel(const int* __restrict__ idx,
                             const float* __restrict__ tok,
                             const float* __restrict__ pos,
                             const float* __restrict__ phase,
                             float* __restrict__ x) {
    int row = blockIdx.x;
    int l   = row % SEQL;
    int t   = idx[row];
    for (int d = threadIdx.x; d < DMODEL; d += blockDim.x) {
        float phi = tanhf(phase[d]) * 3.14159265358979323846f;
        float fac = cosf(phi) - sinf(phi);
        x[(long)row * DMODEL + d] =
            (tok[(long)t * DMODEL + d] + pos[(long)l * DMODEL + d]) * fac;
    }
}

// ---------------- LayerNorm (fp32 in, fp16 out) ----------------
__global__ void ln_kernel(const float* __restrict__ x,
                          const float* __restrict__ w,
                          const float* __restrict__ b,
                          __half* __restrict__ o) {
    int row = blockIdx.x;
    const float* xr = x + (long)row * DMODEL;
    int tid = threadIdx.x;
    float s = 0.f, s2 = 0.f;
    float v[4];
#pragma unroll
    for (int j = 0; j < 4; j++) {
        v[j] = xr[tid + 256 * j];
        s += v[j]; s2 += v[j] * v[j];
    }
    __shared__ float r1[256], r2[256];
    r1[tid] = s; r2[tid] = s2;
    __syncthreads();
    for (int off = 128; off > 0; off >>= 1) {
        if (tid < off) { r1[tid] += r1[tid + off]; r2[tid] += r2[tid + off]; }
        __syncthreads();
    }
    float mean = r1[0] * (1.0f / DMODEL);
    float var  = r2[0] * (1.0f / DMODEL) - mean * mean;
    float rstd = rsqrtf(var + 1e-5f);
    __half* orow = o + (long)row * DMODEL;
#pragma unroll
    for (int j = 0; j < 4; j++) {
        int d = tid + 256 * j;
        orow[d] = __float2half_rn((v[j] - mean) * rstd * w[d] + b[d]);
    }
}

// ---------------- Fused flash attention (fp16 MMA + ldmatrix) ---------------
// grid: (8 q-tiles, 32 batch-heads), 256 threads (8 warps x 16 q-rows).
static constexpr int FA_K_OFF  = 0;
static constexpr int FA_V_OFF  = 128 * 72;
static constexpr int FA_VT_OFF = 2 * 128 * 72;
static constexpr int FA_P_OFF  = 2 * 128 * 72 + 64 * 136;
static constexpr int FA_HALVES = FA_P_OFF + 128 * 136;
static constexpr int FA_SMEM   = FA_HALVES * 2;                   // 89088 B

__global__ __launch_bounds__(256)
void flash_attn_kernel(const __half* __restrict__ qkv, __half* __restrict__ o) {
    extern __shared__ __half fh[];
    __half* Kt   = fh + FA_K_OFF;
    __half* Vraw = fh + FA_V_OFF;
    __half* VtT  = fh + FA_VT_OFF;
    __half* Pu   = fh + FA_P_OFF;
    __half* Qs   = Pu;                     // Q staging reuses P region

    const int qt = blockIdx.x;
    const int bh = blockIdx.y;
    const int b  = bh >> 4;
    const int h  = bh & 15;

    const int tid  = threadIdx.x;
    const int wid  = tid >> 5;
    const int lane = tid & 31;
    const int g = lane >> 2, tig = lane & 3;

    const int lrow  = lane & 7;
    const int a_row = ((lane >> 3) & 1) * 8;
    const int a_k   = (lane >> 4) * 8;
    const int b_row = (lane >> 4) * 8;
    const int b_k   = ((lane >> 3) & 1) * 8;

    const __half* base = qkv + ((long)b * SEQL) * (3 * DMODEL) + h * HEADDIM;

    // ---- stage Q tile
    {
        int r = tid >> 1, hp = tid & 1;
        const __half* src = base + (long)(qt * 128 + r) * (3 * DMODEL) + hp * 32;
        uint32_t dst = smem_u32(&Qs[r * 72 + hp * 32]);
#pragma unroll
        for (int i = 0; i < 4; i++) cp16(dst + i * 16, src + i * 8);
    }
    CP_COMMIT(); CP_WAIT0(); __syncthreads();

    const __half2 qscale = __floats2half2_rn(0.125f, 0.125f);
    uint32_t qf[4][4];
    {
        uint32_t qbase = smem_u32(Qs) +
            ((wid * 16 + a_row + lrow) * 72 + a_k) * 2;
#pragma unroll
        for (int ks = 0; ks < 4; ks++) {
            uint32_t r[4];
            ldsm_x4(r, qbase + ks * 32);
#pragma unroll
            for (int z = 0; z < 4; z++) {
                __half2 hv = __hmul2(*(__half2*)&r[z], qscale);
                qf[ks][z] = *(uint32_t*)&hv;
            }
        }
    }
    __syncthreads();

    float mold0 = -INFINITY, mold1 = -INFINITY;
    float l0 = 0.f, l1 = 0.f;
    float oacc[8][4];
#pragma unroll
    for (int n = 0; n < 8; n++)
#pragma unroll
        for (int r = 0; r < 4; r++) oacc[n][r] = 0.f;

    const uint32_t kt_b_base  = smem_u32(Kt)  + ((b_row + lrow) * 72 + b_k) * 2;
    const uint32_t vt_b_base  = smem_u32(VtT) + ((b_row + lrow) * 136 + b_k) * 2;
    const uint32_t pu_a_base  = smem_u32(Pu) +
        ((wid * 16 + a_row + lrow) * 136 + a_k) * 2;

    for (int kt = 0; kt <= qt; kt++) {
        {
            int r = tid >> 1, hp = tid & 1;
            const __half* ksrc = base + (long)(kt * 128 + r) * (3 * DMODEL) + DMODEL + hp * 32;
            const __half* vsrc = base + (long)(kt * 128 + r) * (3 * DMODEL) + 2 * DMODEL + hp * 32;
            uint32_t kd = smem_u32(&Kt[r * 72 + hp * 32]);
            uint32_t vd = smem_u32(&Vraw[r * 72 + hp * 32]);
#pragma unroll
            for (int i = 0; i < 4; i++) cp16(kd + i * 16, ksrc + i * 8);
#pragma unroll
            for (int i = 0; i < 4; i++) cp16(vd + i * 16, vsrc + i * 8);
        }
        CP_COMMIT(); CP_WAIT0(); __syncthreads();

        {
            int r = tid >> 1, hp = tid & 1;
            const __half* vr = &Vraw[r * 72 + hp * 32];
#pragma unroll
            for (int j = 0; j < 32; j++)
                VtT[(hp * 32 + j) * 136 + r] = vr[j];
        }
        __syncthreads();

        float sacc[16][4];
#pragma unroll
        for (int n = 0; n < 16; n++)
#pragma unroll
            for (int r = 0; r < 4; r++) sacc[n][r] = 0.f;
#pragma unroll
        for (int ntp = 0; ntp < 8; ntp++) {
            uint32_t baddr = kt_b_base + ntp * (16 * 72 * 2);
#pragma unroll
            for (int ks = 0; ks < 4; ks++) {
                uint32_t r[4];
                ldsm_x4(r, baddr + ks * 32);
                mma_f16(sacc[2 * ntp    ], qf[ks], r);
                mma_f16(sacc[2 * ntp + 1], qf[ks], r + 2);
            }
        }

        if (kt == qt) {
            int r0 = wid * 16 + g, r1 = r0 + 8;
#pragma unroll
            for (int nt = 0; nt < 16; nt++) {
                int c0 = nt * 8 + tig * 2;
                if (c0     > r0) sacc[nt][0] = -INFINITY;
                if (c0 + 1 > r0) sacc[nt][1] = -INFINITY;
                if (c0     > r1) sacc[nt][2] = -INFINITY;
                if (c0 + 1 > r1) sacc[nt][3] = -INFINITY;
            }
        }

        float tm0 = -INFINITY, tm1 = -INFINITY;
#pragma unroll
        for (int nt = 0; nt < 16; nt++) {
            tm0 = fmaxf(tm0, fmaxf(sacc[nt][0], sacc[nt][1]));
            tm1 = fmaxf(tm1, fmaxf(sacc[nt][2], sacc[nt][3]));
        }
        tm0 = fmaxf(tm0, __shfl_xor_sync(0xffffffffu, tm0, 1));
        tm0 = fmaxf(tm0, __shfl_xor_sync(0xffffffffu, tm0, 2));
        tm1 = fmaxf(tm1, __shfl_xor_sync(0xffffffffu, tm1, 1));
        tm1 = fmaxf(tm1, __shfl_xor_sync(0xffffffffu, tm1, 2));
        float mn0 = fmaxf(mold0, tm0), mn1 = fmaxf(mold1, tm1);
        float a0 = __expf(mold0 - mn0), a1 = __expf(mold1 - mn1);

        float sum0 = 0.f, sum1 = 0.f;
        int prow = wid * 16 + g;
        uint32_t* Pw = (uint32_t*)Pu;
#pragma unroll
        for (int nt = 0; nt < 16; nt++) {
            float p0 = __expf(sacc[nt][0] - mn0);
            float p1 = __expf(sacc[nt][1] - mn0);
            float p2 = __expf(sacc[nt][2] - mn1);
            float p3 = __expf(sacc[nt][3] - mn1);
            sum0 += p0 + p1; sum1 += p2 + p3;
            int c = nt * 4 + tig;
            Pw[(prow    ) * 68 + c] = pack_h2(p0, p1);
            Pw[(prow + 8) * 68 + c] = pack_h2(p2, p3);
        }
        sum0 += __shfl_xor_sync(0xffffffffu, sum0, 1);
        sum0 += __shfl_xor_sync(0xffffffffu, sum0, 2);
        sum1 += __shfl_xor_sync(0xffffffffu, sum1, 1);
        sum1 += __shfl_xor_sync(0xffffffffu, sum1, 2);
        l0 = l0 * a0 + sum0;
        l1 = l1 * a1 + sum1;
#pragma unroll
        for (int nt = 0; nt < 8; nt++) {
            oacc[nt][0] *= a0; oacc[nt][1] *= a0;
            oacc[nt][2] *= a1; oacc[nt][3] *= a1;
        }
        mold0 = mn0; mold1 = mn1;
        __syncthreads();

#pragma unroll
        for (int ks = 0; ks < 8; ks++) {
            uint32_t af[4];
            ldsm_x4(af, pu_a_base + ks * 32);
#pragma unroll
            for (int ntp = 0; ntp < 4; ntp++) {
                uint32_t r[4];
                ldsm_x4(r, vt_b_base + ntp * (16 * 136 * 2) + ks * 32);
                mma_f16(oacc[2 * ntp    ], af, r);
                mma_f16(oacc[2 * ntp + 1], af, r + 2);
            }
        }
        __syncthreads();
    }

    float i0 = 1.0f / l0, i1 = 1.0f / l1;
    int tok = b * SEQL + qt * 128 + wid * 16 + g;
    __half* o0 = o + (long)tok * DMODEL + h * HEADDIM;
    __half* o1 = o0 + 8 * DMODEL;
#pragma unroll
    for (int nt = 0; nt < 8; nt++) {
        int c = nt * 8 + tig * 2;
        *(uint32_t*)&o0[c] = pack_h2(oacc[nt][0] * i0, oacc[nt][1] * i0);
        *(uint32_t*)&o1[c] = pack_h2(oacc[nt][2] * i1, oacc[nt][3] * i1);
    }
}

// ---------------- fp16 mma.sync GEMM (ldmatrix + 3-stage pipeline) ----------
// C[m,n] = sum_k A[m*lda+k] * B[n*sBn+k]  (+bias)(gelu); out fp32(+res) or fp16
// flags: 1 = gelu, 16 = grid swap, 32 = fp16 output
// BM=128, BN=128: 8 warps 2x4, warp tile 64x32.
__global__ __launch_bounds__(256)
void mma_gemm(const __half* __restrict__ A, int lda,
              const __half* __restrict__ Bp, long sBn,
              const float* __restrict__ bias,
              const float* __restrict__ res, int ldr,
              void* __restrict__ Cv, int ldc,
              int K, int flags) {
    constexpr int BM = 128, BN = 128, BK = 32, LDSH = BK + 8;   // 40 halves/row
    constexpr int STAGES = 3;
    extern __shared__ __half smh[];
    __half* As = smh;                           // [STAGES][BM][40]
    __half* Bs = smh + STAGES * BM * LDSH;      // [STAGES][BN][40]

    int bx = blockIdx.x, by = blockIdx.y;
    if (flags & 16) { int t = bx; bx = by; by = t; }
    const int bm0 = by * BM;
    const int bn0 = bx * BN;
    const int T = K / BK;

    const int tid  = threadIdx.x;
    const int w    = tid >> 5;
    const int lane = tid & 31;
    const int wm = w >> 2, wn = w & 3;
    const int g = lane >> 2, tig = lane & 3;

    const int lrow  = lane & 7;
    const int a_row = ((lane >> 3) & 1) * 8;
    const int a_k   = (lane >> 4) * 8;
    const int b_row = (lane >> 4) * 8;
    const int b_k   = ((lane >> 3) & 1) * 8;

    const uint32_t a_base = smem_u32(As) +
        ((wm * 64 + a_row + lrow) * LDSH + a_k) * 2;
    const uint32_t b_base = smem_u32(Bs) +
        ((wn * 32 + b_row + lrow) * LDSH + b_k) * 2;
    constexpr uint32_t ABUF = BM * LDSH * 2;
    constexpr uint32_t BBUF = BN * LDSH * 2;

    float acc[4][4][4];
#pragma unroll
    for (int i = 0; i < 4; i++)
#pragma unroll
        for (int j = 0; j < 4; j++)
#pragma unroll
            for (int r = 0; r < 4; r++) acc[i][j][r] = 0.0f;

    auto load_tile = [&](int it, int buf) {
        const int k0 = it * BK;
#pragma unroll
        for (int t = 0; t < 2; t++) {
            int vv = tid + t * 256;
            int m = vv >> 2, c = vv & 3;
            cp16(smem_u32(&As[(buf * BM + m) * LDSH + c * 8]),
                 A + (long)(bm0 + m) * lda + k0 + c * 8);
        }
#pragma unroll
        for (int t = 0; t < 2; t++) {
            int vv = tid + t * 256;
            int n = vv >> 2, c = vv & 3;
            cp16(smem_u32(&Bs[(buf * BN + n) * LDSH + c * 8]),
                 Bp + (long)(bn0 + n) * sBn + k0 + c * 8);
        }
    };

    load_tile(0, 0);
    CP_COMMIT();
    if (T > 1) { load_tile(1, 1); CP_COMMIT(); }

    for (int it = 0; it < T; it++) {
        if (it + 1 < T) { CP_WAIT1(); } else { CP_WAIT0(); }
        __syncthreads();   // tile `it` visible; fences compute of it-1
        if (it + 2 < T) { load_tile(it + 2, (it + 2) % STAGES); CP_COMMIT(); }

        const int buf = it % STAGES;
        const uint32_t ab = a_base + buf * ABUF;
        const uint32_t bb = b_base + buf * BBUF;

#pragma unroll
        for (int ks = 0; ks < 2; ks++) {
            uint32_t af[4][4];
#pragma unroll
            for (int i = 0; i < 4; i++)
                ldsm_x4(af[i], ab + i * (16 * LDSH * 2) + ks * 32);
            uint32_t bf[4][4];                  // 2 ldmatrix cover 4 n8 tiles
            ldsm_x4(bf[0], bb + ks * 32);
            ldsm_x4(bf[2], bb + 16 * LDSH * 2 + ks * 32);
#pragma unroll
            for (int i = 0; i < 4; i++) {
                mma_f16(acc[i][0], af[i], bf[0]);
                mma_f16(acc[i][1], af[i], bf[0] + 2);
                mma_f16(acc[i][2], af[i], bf[2]);
                mma_f16(acc[i][3], af[i], bf[2] + 2);
            }
        }
    }

    // epilogue -----------------------------------------------------------
#pragma unroll
    for (int i = 0; i < 4; i++) {
        int r0 = bm0 + wm * 64 + i * 16 + g;
#pragma unroll
        for (int j = 0; j < 4; j++) {
            int c = bn0 + wn * 32 + j * 8 + tig * 2;
            float e00 = acc[i][j][0], e01 = acc[i][j][1];
            float e10 = acc[i][j][2], e11 = acc[i][j][3];
            if (bias) {
                float2 bb2 = *reinterpret_cast<const float2*>(bias + c);
                e00 += bb2.x; e01 += bb2.y; e10 += bb2.x; e11 += bb2.y;
            }
            if (flags & 1) {
                e00 = gelu_exact(e00); e01 = gelu_exact(e01);
                e10 = gelu_exact(e10); e11 = gelu_exact(e11);
            }
            if (flags & 32) {
                __half* C = (__half*)Cv;
                *(uint32_t*)&C[(long)r0 * ldc + c]       = pack_h2(e00, e01);
                *(uint32_t*)&C[(long)(r0 + 8) * ldc + c] = pack_h2(e10, e11);
            } else {
                float* C = (float*)Cv;
                if (res) {
                    float2 ra = *reinterpret_cast<const float2*>(
                        res + (long)r0 * ldr + c);
                    float2 rb = *reinterpret_cast<const float2*>(
                        res + (long)(r0 + 8) * ldr + c);
                    e00 += ra.x; e01 += ra.y; e10 += rb.x; e11 += rb.y;
                }
                *reinterpret_cast<float2*>(C + (long)r0 * ldc + c) =
                    make_float2(e00, e01);
                *reinterpret_cast<float2*>(C + (long)(r0 + 8) * ldc + c) =
                    make_float2(e10, e11);
            }
        }
    }
}

// ---------------- host-side launch helper ----------------
static constexpr int GEMM_SMEM = 3 * (128 * 40 + 128 * 40) * 2;  // 61440

static void tgemm(const __half* A, int lda, const __half* B, long sBn,
                  const float* bias, const float* res, int ldr,
                  void* C, int ldc, int M, int N, int K, int flags) {
    dim3 gdim;
    if (flags & 16) gdim = dim3(M / 128, N / 128, 1);
    else            gdim = dim3(N / 128, M / 128, 1);
    mma_gemm<<<gdim, 256, GEMM_SMEM>>>(A, lda, B, sBn, bias, res, ldr,
                                       C, ldc, K, flags);
}

// ---------------- entry point ----------------
extern "C" void kernel_launch(void* const* d_in, const int* in_sizes, int n_in,
                              void* d_out, int out_size) {
    const int*   idx   = (const int*)  d_in[0];
    const float* tok   = (const float*)d_in[1];
    const float* pos   = (const float*)d_in[2];
    const float* phase = (const float*)d_in[3];
    const float* ln1w  = (const float*)d_in[4];
    const float* ln1b  = (const float*)d_in[5];

    const float *ln2w, *ln2b;
    int wbase;
    if (in_sizes[6] == DEPTH * DMODEL) {        // dict order
        ln2w = (const float*)d_in[6];
        ln2b = (const float*)d_in[7];
        wbase = 8;
    } else {                                     // signature order fallback
        ln2w = (const float*)d_in[22];
        ln2b = (const float*)d_in[23];
        wbase = 6;
    }
    const float* Wq = (const float*)d_in[wbase + 0];
    const float* bq = (const float*)d_in[wbase + 1];
    const float* Bq = (const float*)d_in[wbase + 2];
    const float* Aq = (const float*)d_in[wbase + 3];
    const float* Wk = (const float*)d_in[wbase + 4];
    const float* bk = (const float*)d_in[wbase + 5];
    const float* Bk = (const float*)d_in[wbase + 6];
    const float* Ak = (const float*)d_in[wbase + 7];
    const float* Wv = (const float*)d_in[wbase + 8];
    const float* bv = (const float*)d_in[wbase + 9];
    const float* Bv = (const float*)d_in[wbase + 10];
    const float* Av = (const float*)d_in[wbase + 11];
    const float* Wo = (const float*)d_in[wbase + 12];
    const float* bo = (const float*)d_in[wbase + 13];
    const float* Bo = (const float*)d_in[wbase + 14];
    const float* Ao = (const float*)d_in[wbase + 15];
    const float* W1 = (const float*)d_in[24];
    const float* b1 = (const float*)d_in[25];
    const float* W2 = (const float*)d_in[26];
    const float* b2 = (const float*)d_in[27];
    const float* lnfw = (const float*)d_in[28];
    const float* lnfb = (const float*)d_in[29];
    const float* headW = (const float*)d_in[30];
    float* out = (float*)d_out;

    float *x, *bqkv;
    __half *h, *qkv, *o, *ff, *wqkv, *wo, *w1c, *w2c, *headc;
    cudaGetSymbolAddress((void**)&x,    g_x);
    cudaGetSymbolAddress((void**)&h,    g_h);
    cudaGetSymbolAddress((void**)&qkv,  g_qkv);
    cudaGetSymbolAddress((void**)&o,    g_o);
    cudaGetSymbolAddress((void**)&ff,   g_ff);
    cudaGetSymbolAddress((void**)&wqkv, g_wqkv);
    cudaGetSymbolAddress((void**)&bqkv, g_bqkv);
    cudaGetSymbolAddress((void**)&wo,   g_wo);
    cudaGetSymbolAddress((void**)&w1c,  g_w1c);
    cudaGetSymbolAddress((void**)&w2c,  g_w2c);
    cudaGetSymbolAddress((void**)&headc, g_headc);

    cudaFuncSetAttribute(flash_attn_kernel,
                         cudaFuncAttributeMaxDynamicSharedMemorySize, FA_SMEM);
    cudaFuncSetAttribute(mma_gemm,
                         cudaFuncAttributeMaxDynamicSharedMemorySize, GEMM_SMEM);

    const int D = DMODEL;
    const long DD = (long)D * D;

    // 1) weight prep: LoRA folds + fp16 conversions
    {
        int nblk = (int)(DEPTH * DD / 4 / 256);
        weff_qkv_kernel<<<3 * nblk, 256>>>(Wq, Aq, Bq, Wk, Ak, Bk, Wv, Av, Bv,
                                           wqkv);
        weff_kernel<<<nblk, 256>>>(Wo, Ao, Bo, wo, DD, 0);
        bias_concat_kernel<<<DEPTH * 3 * D / 256, 256>>>(bq, bk, bv, bqkv);
        conv_f16_kernel<<<DEPTH * HIDDEN * D / 1024, 256>>>(W1, w1c);
        conv_f16_kernel<<<DEPTH * HIDDEN * D / 1024, 256>>>(W2, w2c);
        conv_f16_kernel<<<VOCAB * D / 1024, 256>>>(headW, headc);
    }
    embed_kernel<<<NTOK, 256>>>(idx, tok, pos, phase, x);

    // 2) transformer layers
    for (int i = 0; i < DEPTH; i++) {
        const __half* wqkv_i = wqkv + (long)i * 3 * DD;
        const __half* woi    = wo + (long)i * DD;

        ln_kernel<<<NTOK, 256>>>(x, ln1w + i * D, ln1b + i * D, h);

        // fused QKV (fp16 output)
        tgemm(h, D, wqkv_i, D, bqkv + (long)i * 3 * D, nullptr, 0,
              qkv, 3 * D, NTOK, 3 * D, D, /*flags=*/32);

        flash_attn_kernel<<<dim3(SEQL / 128, BATCH * NHEAD), 256, FA_SMEM>>>(
            qkv, o);

        // x = x + o @ Wo_eff^T + bo  (fp32 output + residual)
        tgemm(o, D, woi, D, bo + i * D, x, D, x, D, NTOK, D, D, 0);

        ln_kernel<<<NTOK, 256>>>(x, ln2w + i * D, ln2b + i * D, h);

        // ff = fp16(gelu(h @ W1^T + b1))
        tgemm(h, D, w1c + (long)i * HIDDEN * D, D, b1 + i * HIDDEN,
              nullptr, 0, ff, HIDDEN, NTOK, HIDDEN, D, /*flags=*/1 | 32);
        // x = x + ff @ W2^T + b2
        tgemm(ff, HIDDEN, w2c + (long)i * D * HIDDEN, HIDDEN, b2 + i * D,
              x, D, x, D, NTOK, D, HIDDEN, 0);
    }

    // 3) final LN + LM head (grid-swapped for L2 B reuse)
    ln_kernel<<<NTOK, 256>>>(x, lnfw, lnfb, h);
    tgemm(h, D, headc, D, nullptr, nullptr, 0, out, VOCAB,
          NTOK, VOCAB, D, /*flags=*/16);
}

// round 13
// speedup vs baseline: 1.0546x; 1.0403x over previous
#include <cuda_runtime.h>
#include <cuda_fp16.h>
#include <cstdint>
#include <math.h>

// ---------------- Problem constants ----------------
#define VOCAB 32000
#define DMODEL 1024
#define DEPTH 6
#define NHEAD 16
#define SEQL 1024
#define BATCH 2
#define LRANK 16
#define HIDDEN 4096
#define HEADDIM 64
#define NTOK (BATCH * SEQL)          // 2048
#define SCALING 0.5f                  // 8.0 / 16

// ---------------- Scratch (device globals; no allocation allowed) -------------
static __device__ float  g_x  [NTOK * DMODEL];
static __device__ __half g_h  [NTOK * DMODEL];
static __device__ __half g_qkv[NTOK * 3 * DMODEL];
static __device__ __half g_o  [NTOK * DMODEL];
static __device__ __half g_ff [NTOK * HIDDEN];
static __device__ __half g_wqkv[DEPTH * 3 * DMODEL * DMODEL];
static __device__ float  g_bqkv[DEPTH * 3 * DMODEL];
static __device__ __half g_wo  [DEPTH * DMODEL * DMODEL];
static __device__ __half g_w1c [DEPTH * HIDDEN * DMODEL];
static __device__ __half g_w2c [DEPTH * DMODEL * HIDDEN];
static __device__ __half g_headc[(long)VOCAB * DMODEL];

// ---------------- small PTX helpers (baseline ISA only) ----------------
__device__ __forceinline__ uint32_t smem_u32(const void* p) {
    uint32_t a;
    asm("{ .reg .u64 t; cvta.to.shared.u64 t, %1; cvt.u32.u64 %0, t; }"
        : "=r"(a) : "l"(p));
    return a;
}
__device__ __forceinline__ void cp16(uint32_t dst, const void* src) {
    asm volatile("cp.async.cg.shared.global [%0], [%1], 16;"
                 :: "r"(dst), "l"(src));
}
#define CP_COMMIT() asm volatile("cp.async.commit_group;" ::: "memory")
#define CP_WAIT1()  asm volatile("cp.async.wait_group 1;"  ::: "memory")
#define CP_WAIT0()  asm volatile("cp.async.wait_group 0;"  ::: "memory")

// fp16 MMA: m16n8k16, fp32 accumulate
__device__ __forceinline__ void mma_f16(float* d, const uint32_t* a,
                                        const uint32_t* b) {
    asm volatile(
        "mma.sync.aligned.m16n8k16.row.col.f32.f16.f16.f32 "
        "{%0,%1,%2,%3}, {%4,%5,%6,%7}, {%8,%9}, {%0,%1,%2,%3};"
        : "+f"(d[0]), "+f"(d[1]), "+f"(d[2]), "+f"(d[3])
        : "r"(a[0]), "r"(a[1]), "r"(a[2]), "r"(a[3]), "r"(b[0]), "r"(b[1]));
}

// ldmatrix x4: loads 4 8x8 fp16 matrices; per-thread address = one 16B row
__device__ __forceinline__ void ldsm_x4(uint32_t* r, uint32_t addr) {
    asm volatile("ldmatrix.sync.aligned.m8n8.x4.shared.b16 {%0,%1,%2,%3}, [%4];"
                 : "=r"(r[0]), "=r"(r[1]), "=r"(r[2]), "=r"(r[3])
                 : "r"(addr));
}

// ---------------- helpers ----------------
__device__ __forceinline__ float gelu_exact(float x) {
    return 0.5f * x * (1.0f + erff(x * 0.70710678118654752440f));
}
__device__ __forceinline__ uint32_t pack_h2(float a, float b) {
    __half2 h = __floats2half2_rn(a, b);
    return *reinterpret_cast<uint32_t*>(&h);
}

// ---------------- fp16 round-copy (for W1/W2/headW) ----------------
__global__ void conv_f16_kernel(const float* __restrict__ src,
                                __half* __restrict__ dst) {
    long e4 = ((long)blockIdx.x * 256 + threadIdx.x) * 4;
    float4 f = *reinterpret_cast<const float4*>(src + e4);
    uint2 u;
    u.x = pack_h2(f.x, f.y);
    u.y = pack_h2(f.z, f.w);
    *reinterpret_cast<uint2*>(dst + e4) = u;
}

// ---------------- LoRA fold body (writes fp16) ----------------
__device__ __forceinline__ void weff_body(long e4,
                                          const float* __restrict__ W,
                                          const float* __restrict__ Am,
                                          const float* __restrict__ Bm,
                                          __half* __restrict__ out,
                                          long outLS, long outOff) {
    const int DD4 = DMODEL * DMODEL / 4;
    int layer = (int)(e4 / DD4);
    int rem4  = (int)(e4 % DD4);
    int orow  = rem4 / (DMODEL / 4);
    int ic4   = (rem4 % (DMODEL / 4)) * 4;
    const float* a  = Am + (long)layer * DMODEL * LRANK + (long)orow * LRANK;
    const float* bb = Bm + (long)layer * LRANK * DMODEL + ic4;
    float4 s = make_float4(0.f, 0.f, 0.f, 0.f);
#pragma unroll
    for (int r = 0; r < LRANK; r++) {
        float4 bv = *reinterpret_cast<const float4*>(bb + (long)r * DMODEL);
        float av = a[r];
        s.x += av * bv.x; s.y += av * bv.y; s.z += av * bv.z; s.w += av * bv.w;
    }
    float4 wv = *reinterpret_cast<const float4*>(
        W + (long)layer * DMODEL * DMODEL + rem4 * 4);
    uint2 u;
    u.x = pack_h2(wv.x + SCALING * s.x, wv.y + SCALING * s.y);
    u.y = pack_h2(wv.z + SCALING * s.z, wv.w + SCALING * s.w);
    *reinterpret_cast<uint2*>(out + (long)layer * outLS + outOff + rem4 * 4) = u;
}

__global__ void weff_qkv_kernel(const float* __restrict__ Wq, const float* __restrict__ Aq, const float* __restrict__ Bq,
                                const float* __restrict__ Wk, const float* __restrict__ Ak, const float* __restrict__ Bk,
                                const float* __restrict__ Wv, const float* __restrict__ Av, const float* __restrict__ Bv,
                                __half* __restrict__ out) {
    const int nblk = DEPTH * DMODEL * DMODEL / 4 / 256;
    int seg = blockIdx.x / nblk;
    long e4 = (long)(blockIdx.x % nblk) * 256 + threadIdx.x;
    const long DD = (long)DMODEL * DMODEL;
    const float *W = (seg == 0) ? Wq : (seg == 1 ? Wk : Wv);
    const float *A = (seg == 0) ? Aq : (seg == 1 ? Ak : Av);
    const float *B = (seg == 0) ? Bq : (seg == 1 ? Bk : Bv);
    weff_body(e4, W, A, B, out, 3 * DD, seg * DD);
}

__global__ void weff_kernel(const float* __restrict__ W,
                            const float* __restrict__ Am,
                            const float* __restrict__ Bm,
                            __half* __restrict__ out,
                            long outLS, long outOff) {
    long e4 = (long)blockIdx.x * 256 + threadIdx.x;
    weff_body(e4, W, Am, Bm, out, outLS, outOff);
}

// ---------------- bias concat for fused QKV ----------------
__global__ void bias_concat_kernel(const float* __restrict__ bq,
                                   const float* __restrict__ bk,
                                   const float* __restrict__ bv,
                                   float* __restrict__ out) {
    int e = blockIdx.x * 256 + threadIdx.x;
    int layer = e / (3 * DMODEL);
    int r = e % (3 * DMODEL);
    const float* src = (r < DMODEL) ? bq : (r < 2 * DMODEL ? bk : bv);
    out[e] = src[layer * DMODEL + (r % DMODEL)];
}

// ---------------- Embedding + phase rotator (x stays fp32) ----------------
__global__ void embed_kernel(const int* __restrict__ idx,
                             const float* __restrict__ tok,
                             const float* __restrict__ pos,
                             const float* __restrict__ phase,
                             float* __restrict__ x) {
    int row = blockIdx.x;
    int l   = row % SEQL;
    int t   = idx[row];
    for (int d = threadIdx.x; d < DMODEL; d += blockDim.x) {
        float phi = tanhf(phase[d]) * 3.14159265358979323846f;
        float fac = cosf(phi) - sinf(phi);
        x[(long)row * DMODEL + d] =
            (tok[(long)t * DMODEL + d] + pos[(long)l * DMODEL + d]) * fac;
    }
}

// ---------------- LayerNorm (fp32 in, fp16 out) ----------------
__global__ void ln_kernel(const float* __restrict__ x,
                          const float* __restrict__ w,
                          const float* __restrict__ b,
                          __half* __restrict__ o) {
    int row = blockIdx.x;
    const float* xr = x + (long)row * DMODEL;
    int tid = threadIdx.x;
    float s = 0.f, s2 = 0.f;
    float v[4];
#pragma unroll
    for (int j = 0; j < 4; j++) {
        v[j] = xr[tid + 256 * j];
        s += v[j]; s2 += v[j] * v[j];
    }
    __shared__ float r1[256], r2[256];
    r1[tid] = s; r2[tid] = s2;
    __syncthreads();
    for (int off = 128; off > 0; off >>= 1) {
        if (tid < off) { r1[tid] += r1[tid + off]; r2[tid] += r2[tid + off]; }
        __syncthreads();
    }
    float mean = r1[0] * (1.0f / DMODEL);
    float var  = r2[0] * (1.0f / DMODEL) - mean * mean;
    float rstd = rsqrtf(var + 1e-5f);
    __half* orow = o + (long)row * DMODEL;
#pragma unroll
    for (int j = 0; j < 4; j++) {
        int d = tid + 256 * j;
        orow[d] = __float2half_rn((v[j] - mean) * rstd * w[d] + b[d]);
    }
}

// ---------------- Fused flash attention (fp16 MMA + ldmatrix) ---------------
// grid: (8 q-tiles, 32 batch-heads), 256 threads (8 warps x 16 q-rows).
// Blocks take q-tiles in DESCENDING work order (LPT packing for causal skew).
static constexpr int FA_K_OFF  = 0;
static constexpr int FA_V_OFF  = 128 * 72;
static constexpr int FA_VT_OFF = 2 * 128 * 72;
static constexpr int FA_P_OFF  = 2 * 128 * 72 + 64 * 136;
static constexpr int FA_HALVES = FA_P_OFF + 128 * 136;
static constexpr int FA_SMEM   = FA_HALVES * 2;                   // 89088 B

__global__ __launch_bounds__(256)
void flash_attn_kernel(const __half* __restrict__ qkv, __half* __restrict__ o) {
    extern __shared__ __half fh[];
    __half* Kt   = fh + FA_K_OFF;
    __half* Vraw = fh + FA_V_OFF;
    __half* VtT  = fh + FA_VT_OFF;
    __half* Pu   = fh + FA_P_OFF;
    __half* Qs   = Pu;                     // Q staging reuses P region

    const int qt = (int)gridDim.x - 1 - (int)blockIdx.x;  // heavy tiles first
    const int bh = blockIdx.y;
    const int b  = bh >> 4;
    const int h  = bh & 15;

    const int tid  = threadIdx.x;
    const int wid  = tid >> 5;
    const int lane = tid & 31;
    const int g = lane >> 2, tig = lane & 3;

    const int lrow  = lane & 7;
    const int a_row = ((lane >> 3) & 1) * 8;
    const int a_k   = (lane >> 4) * 8;
    const int b_row = (lane >> 4) * 8;
    const int b_k   = ((lane >> 3) & 1) * 8;

    const __half* base = qkv + ((long)b * SEQL) * (3 * DMODEL) + h * HEADDIM;

    // ---- stage Q tile
    {
        int r = tid >> 1, hp = tid & 1;
        const __half* src = base + (long)(qt * 128 + r) * (3 * DMODEL) + hp * 32;
        uint32_t dst = smem_u32(&Qs[r * 72 + hp * 32]);
#pragma unroll
        for (int i = 0; i < 4; i++) cp16(dst + i * 16, src + i * 8);
    }
    CP_COMMIT(); CP_WAIT0(); __syncthreads();

    const __half2 qscale = __floats2half2_rn(0.125f, 0.125f);
    uint32_t qf[4][4];
    {
        uint32_t qbase = smem_u32(Qs) +
            ((wid * 16 + a_row + lrow) * 72 + a_k) * 2;
#pragma unroll
        for (int ks = 0; ks < 4; ks++) {
            uint32_t r[4];
            ldsm_x4(r, qbase + ks * 32);
#pragma unroll
            for (int z = 0; z < 4; z++) {
                __half2 hv = __hmul2(*(__half2*)&r[z], qscale);
                qf[ks][z] = *(uint32_t*)&hv;
            }
        }
    }
    __syncthreads();

    float mold0 = -INFINITY, mold1 = -INFINITY;
    float l0 = 0.f, l1 = 0.f;
    float oacc[8][4];
#pragma unroll
    for (int n = 0; n < 8; n++)
#pragma unroll
        for (int r = 0; r < 4; r++) oacc[n][r] = 0.f;

    const uint32_t kt_b_base  = smem_u32(Kt)  + ((b_row + lrow) * 72 + b_k) * 2;
    const uint32_t vt_b_base  = smem_u32(VtT) + ((b_row + lrow) * 136 + b_k) * 2;
    const uint32_t pu_a_base  = smem_u32(Pu) +
        ((wid * 16 + a_row + lrow) * 136 + a_k) * 2;

    for (int kt = 0; kt <= qt; kt++) {
        {
            int r = tid >> 1, hp = tid & 1;
            const __half* ksrc = base + (long)(kt * 128 + r) * (3 * DMODEL) + DMODEL + hp * 32;
            const __half* vsrc = base + (long)(kt * 128 + r) * (3 * DMODEL) + 2 * DMODEL + hp * 32;
            uint32_t kd = smem_u32(&Kt[r * 72 + hp * 32]);
            uint32_t vd = smem_u32(&Vraw[r * 72 + hp * 32]);
#pragma unroll
            for (int i = 0; i < 4; i++) cp16(kd + i * 16, ksrc + i * 8);
#pragma unroll
            for (int i = 0; i < 4; i++) cp16(vd + i * 16, vsrc + i * 8);
        }
        CP_COMMIT(); CP_WAIT0(); __syncthreads();

        {
            int r = tid >> 1, hp = tid & 1;
            const __half* vr = &Vraw[r * 72 + hp * 32];
#pragma unroll
            for (int j = 0; j < 32; j++)
                VtT[(hp * 32 + j) * 136 + r] = vr[j];
        }
        __syncthreads();

        float sacc[16][4];
#pragma unroll
        for (int n = 0; n < 16; n++)
#pragma unroll
            for (int r = 0; r < 4; r++) sacc[n][r] = 0.f;
#pragma unroll
        for (int ntp = 0; ntp < 8; ntp++) {
            uint32_t baddr = kt_b_base + ntp * (16 * 72 * 2);
#pragma unroll
            for (int ks = 0; ks < 4; ks++) {
                uint32_t r[4];
                ldsm_x4(r, baddr + ks * 32);
                mma_f16(sacc[2 * ntp    ], qf[ks], r);
                mma_f16(sacc[2 * ntp + 1], qf[ks], r + 2);
            }
        }

        if (kt == qt) {
            int r0 = wid * 16 + g, r1 = r0 + 8;
#pragma unroll
            for (int nt = 0; nt < 16; nt++) {
                int c0 = nt * 8 + tig * 2;
                if (c0     > r0) sacc[nt][0] = -INFINITY;
                if (c0 + 1 > r0) sacc[nt][1] = -INFINITY;
                if (c0     > r1) sacc[nt][2] = -INFINITY;
                if (c0 + 1 > r1) sacc[nt][3] = -INFINITY;
            }
        }

        float tm0 = -INFINITY, tm1 = -INFINITY;
#pragma unroll
        for (int nt = 0; nt < 16; nt++) {
            tm0 = fmaxf(tm0, fmaxf(sacc[nt][0], sacc[nt][1]));
            tm1 = fmaxf(tm1, fmaxf(sacc[nt][2], sacc[nt][3]));
        }
        tm0 = fmaxf(tm0, __shfl_xor_sync(0xffffffffu, tm0, 1));
        tm0 = fmaxf(tm0, __shfl_xor_sync(0xffffffffu, tm0, 2));
        tm1 = fmaxf(tm1, __shfl_xor_sync(0xffffffffu, tm1, 1));
        tm1 = fmaxf(tm1, __shfl_xor_sync(0xffffffffu, tm1, 2));
        float mn0 = fmaxf(mold0, tm0), mn1 = fmaxf(mold1, tm1);
        float a0 = __expf(mold0 - mn0), a1 = __expf(mold1 - mn1);

        float sum0 = 0.f, sum1 = 0.f;
        int prow = wid * 16 + g;
        uint32_t* Pw = (uint32_t*)Pu;
#pragma unroll
        for (int nt = 0; nt < 16; nt++) {
            float p0 = __expf(sacc[nt][0] - mn0);
            float p1 = __expf(sacc[nt][1] - mn0);
            float p2 = __expf(sacc[nt][2] - mn1);
            float p3 = __expf(sacc[nt][3] - mn1);
            sum0 += p0 + p1; sum1 += p2 + p3;
            int c = nt * 4 + tig;
            Pw[(prow    ) * 68 + c] = pack_h2(p0, p1);
            Pw[(prow + 8) * 68 + c] = pack_h2(p2, p3);
        }
        sum0 += __shfl_xor_sync(0xffffffffu, sum0, 1);
        sum0 += __shfl_xor_sync(0xffffffffu, sum0, 2);
        sum1 += __shfl_xor_sync(0xffffffffu, sum1, 1);
        sum1 += __shfl_xor_sync(0xffffffffu, sum1, 2);
        l0 = l0 * a0 + sum0;
        l1 = l1 * a1 + sum1;
#pragma unroll
        for (int nt = 0; nt < 8; nt++) {
            oacc[nt][0] *= a0; oacc[nt][1] *= a0;
            oacc[nt][2] *= a1; oacc[nt][3] *= a1;
        }
        mold0 = mn0; mold1 = mn1;
        __syncthreads();

#pragma unroll
        for (int ks = 0; ks < 8; ks++) {
            uint32_t af[4];
            ldsm_x4(af, pu_a_base + ks * 32);
#pragma unroll
            for (int ntp = 0; ntp < 4; ntp++) {
                uint32_t r[4];
                ldsm_x4(r, vt_b_base + ntp * (16 * 136 * 2) + ks * 32);
                mma_f16(oacc[2 * ntp    ], af, r);
                mma_f16(oacc[2 * ntp + 1], af, r + 2);
            }
        }
        __syncthreads();
    }

    float i0 = 1.0f / l0, i1 = 1.0f / l1;
    int tok = b * SEQL + qt * 128 + wid * 16 + g;
    __half* o0 = o + (long)tok * DMODEL + h * HEADDIM;
    __half* o1 = o0 + 8 * DMODEL;
#pragma unroll
    for (int nt = 0; nt < 8; nt++) {
        int c = nt * 8 + tig * 2;
        *(uint32_t*)&o0[c] = pack_h2(oacc[nt][0] * i0, oacc[nt][1] * i0);
        *(uint32_t*)&o1[c] = pack_h2(oacc[nt][2] * i1, oacc[nt][3] * i1);
    }
}

// ---------------- fp16 mma.sync GEMM (R10 core: 2-stage + ldmatrix) ---------
// C[m,n] = sum_k A[m*lda+k] * B[n*sBn+k]  (+bias)(gelu); out fp32(+res) or fp16
// flags: 1 = gelu, 16 = grid swap, 32 = fp16 output
// BM=128, BN=128, BK=32 halves; 8 warps 2x4; warp tile 64x32.
__global__ __launch_bounds__(256)
void mma_gemm(const __half* __restrict__ A, int lda,
              const __half* __restrict__ Bp, long sBn,
              const float* __restrict__ bias,
              const float* __restrict__ res, int ldr,
              void* __restrict__ Cv, int ldc,
              int K, int flags) {
    constexpr int BM = 128, BN = 128, BK = 32, LDSH = BK + 8;   // 40 halves/row
    extern __shared__ __half smh[];
    __half* As = smh;                         // [2][BM][40]
    __half* Bs = smh + 2 * BM * LDSH;         // [2][BN][40]

    int bx = blockIdx.x, by = blockIdx.y;
    if (flags & 16) { int t = bx; bx = by; by = t; }
    const int bm0 = by * BM;
    const int bn0 = bx * BN;
    const int T = K / BK;

    const int tid  = threadIdx.x;
    const int w    = tid >> 5;
    const int lane = tid & 31;
    const int wm = w >> 2, wn = w & 3;
    const int g = lane >> 2, tig = lane & 3;

    const int lrow  = lane & 7;
    const int a_row = ((lane >> 3) & 1) * 8;
    const int a_k   = (lane >> 4) * 8;
    const int b_row = (lane >> 4) * 8;
    const int b_k   = ((lane >> 3) & 1) * 8;

    const uint32_t a_base = smem_u32(As) +
        ((wm * 64 + a_row + lrow) * LDSH + a_k) * 2;
    const uint32_t b_base = smem_u32(Bs) +
        ((wn * 32 + b_row + lrow) * LDSH + b_k) * 2;
    constexpr uint32_t ABUF = BM * LDSH * 2;
    constexpr uint32_t BBUF = BN * LDSH * 2;

    float acc[4][4][4];
#pragma unroll
    for (int i = 0; i < 4; i++)
#pragma unroll
        for (int j = 0; j < 4; j++)
#pragma unroll
            for (int r = 0; r < 4; r++) acc[i][j][r] = 0.0f;

    auto load_tile = [&](int it, int buf) {
        const int k0 = it * BK;
#pragma unroll
        for (int t = 0; t < 2; t++) {
            int vv = tid + t * 256;
            int m = vv >> 2, c = vv & 3;
            cp16(smem_u32(&As[(buf * BM + m) * LDSH + c * 8]),
                 A + (long)(bm0 + m) * lda + k0 + c * 8);
        }
#pragma unroll
        for (int t = 0; t < 2; t++) {
            int vv = tid + t * 256;
            int n = vv >> 2, c = vv & 3;
            cp16(smem_u32(&Bs[(buf * BN + n) * LDSH + c * 8]),
                 Bp + (long)(bn0 + n) * sBn + k0 + c * 8);
        }
    };

    load_tile(0, 0);
    CP_COMMIT();

    for (int it = 0; it < T; it++) {
        const int buf = it & 1;
        if (it + 1 < T) {
            load_tile(it + 1, buf ^ 1);
            CP_COMMIT();
            CP_WAIT1();
        } else {
            CP_WAIT0();
        }
        __syncthreads();

        const uint32_t ab = a_base + buf * ABUF;
        const uint32_t bb = b_base + buf * BBUF;

#pragma unroll
        for (int ks = 0; ks < 2; ks++) {
            uint32_t af[4][4];
#pragma unroll
            for (int i = 0; i < 4; i++)
                ldsm_x4(af[i], ab + i * (16 * LDSH * 2) + ks * 32);
            uint32_t bf[4][4];                  // 2 ldmatrix cover 4 n8 tiles
            ldsm_x4(bf[0], bb + ks * 32);
            ldsm_x4(bf[2], bb + 16 * LDSH * 2 + ks * 32);
#pragma unroll
            for (int i = 0; i < 4; i++) {
                mma_f16(acc[i][0], af[i], bf[0]);
                mma_f16(acc[i][1], af[i], bf[0] + 2);
                mma_f16(acc[i][2], af[i], bf[2]);
                mma_f16(acc[i][3], af[i], bf[2] + 2);
            }
        }
        __syncthreads();
    }

    // epilogue -----------------------------------------------------------
#pragma unroll
    for (int i = 0; i < 4; i++) {
        int r0 = bm0 + wm * 64 + i * 16 + g;
#pragma unroll
        for (int j = 0; j < 4; j++) {
            int c = bn0 + wn * 32 + j * 8 + tig * 2;
            float e00 = acc[i][j][0], e01 = acc[i][j][1];
            float e10 = acc[i][j][2], e11 = acc[i][j][3];
            if (bias) {
                float2 bb2 = *reinterpret_cast<const float2*>(bias + c);
                e00 += bb2.x; e01 += bb2.y; e10 += bb2.x; e11 += bb2.y;
            }
            if (flags & 1) {
                e00 = gelu_exact(e00); e01 = gelu_exact(e01);
                e10 = gelu_exact(e10); e11 = gelu_exact(e11);
            }
            if (flags & 32) {
                __half* C = (__half*)Cv;
                *(uint32_t*)&C[(long)r0 * ldc + c]       = pack_h2(e00, e01);
                *(uint32_t*)&C[(long)(r0 + 8) * ldc + c] = pack_h2(e10, e11);
            } else {
                float* C = (float*)Cv;
                if (res) {
                    float2 ra = *reinterpret_cast<const float2*>(
                        res + (long)r0 * ldr + c);
                    float2 rb = *reinterpret_cast<const float2*>(
                        res + (long)(r0 + 8) * ldr + c);
                    e00 += ra.x; e01 += ra.y; e10 += rb.x; e11 += rb.y;
                }
                *reinterpret_cast<float2*>(C + (long)r0 * ldc + c) =
                    make_float2(e00, e01);
                *reinterpret_cast<float2*>(C + (long)(r0 + 8) * ldc + c) =
                    make_float2(e10, e11);
            }
        }
    }
}

// ---------------- host-side launch helper ----------------
static constexpr int GEMM_SMEM = (2 * 128 * 40 + 2 * 128 * 40) * 2;  // 40960

static void tgemm(const __half* A, int lda, const __half* B, long sBn,
                  const float* bias, const float* res, int ldr,
                  void* C, int ldc, int M, int N, int K, int flags) {
    dim3 gdim;
    if (flags & 16) gdim = dim3(M / 128, N / 128, 1);
    else            gdim = dim3(N / 128, M / 128, 1);
    mma_gemm<<<gdim, 256, GEMM_SMEM>>>(A, lda, B, sBn, bias, res, ldr,
                                       C, ldc, K, flags);
}

// ---------------- entry point ----------------
extern "C" void kernel_launch(void* const* d_in, const int* in_sizes, int n_in,
                              void* d_out, int out_size) {
    const int*   idx   = (const int*)  d_in[0];
    const float* tok   = (const float*)d_in[1];
    const float* pos   = (const float*)d_in[2];
    const float* phase = (const float*)d_in[3];
    const float* ln1w  = (const float*)d_in[4];
    const float* ln1b  = (const float*)d_in[5];

    const float *ln2w, *ln2b;
    int wbase;
    if (in_sizes[6] == DEPTH * DMODEL) {        // dict order
        ln2w = (const float*)d_in[6];
        ln2b = (const float*)d_in[7];
        wbase = 8;
    } else {                                     // signature order fallback
        ln2w = (const float*)d_in[22];
        ln2b = (const float*)d_in[23];
        wbase = 6;
    }
    const float* Wq = (const float*)d_in[wbase + 0];
    const float* bq = (const float*)d_in[wbase + 1];
    const float* Bq = (const float*)d_in[wbase + 2];
    const float* Aq = (const float*)d_in[wbase + 3];
    const float* Wk = (const float*)d_in[wbase + 4];
    const float* bk = (const float*)d_in[wbase + 5];
    const float* Bk = (const float*)d_in[wbase + 6];
    const float* Ak = (const float*)d_in[wbase + 7];
    const float* Wv = (const float*)d_in[wbase + 8];
    const float* bv = (const float*)d_in[wbase + 9];
    const float* Bv = (const float*)d_in[wbase + 10];
    const float* Av = (const float*)d_in[wbase + 11];
    const float* Wo = (const float*)d_in[wbase + 12];
    const float* bo = (const float*)d_in[wbase + 13];
    const float* Bo = (const float*)d_in[wbase + 14];
    const float* Ao = (const float*)d_in[wbase + 15];
    const float* W1 = (const float*)d_in[24];
    const float* b1 = (const float*)d_in[25];
    const float* W2 = (const float*)d_in[26];
    const float* b2 = (const float*)d_in[27];
    const float* lnfw = (const float*)d_in[28];
    const float* lnfb = (const float*)d_in[29];
    const float* headW = (const float*)d_in[30];
    float* out = (float*)d_out;

    float *x, *bqkv;
    __half *h, *qkv, *o, *ff, *wqkv, *wo, *w1c, *w2c, *headc;
    cudaGetSymbolAddress((void**)&x,    g_x);
    cudaGetSymbolAddress((void**)&h,    g_h);
    cudaGetSymbolAddress((void**)&qkv,  g_qkv);
    cudaGetSymbolAddress((void**)&o,    g_o);
    cudaGetSymbolAddress((void**)&ff,   g_ff);
    cudaGetSymbolAddress((void**)&wqkv, g_wqkv);
    cudaGetSymbolAddress((void**)&bqkv, g_bqkv);
    cudaGetSymbolAddress((void**)&wo,   g_wo);
    cudaGetSymbolAddress((void**)&w1c,  g_w1c);
    cudaGetSymbolAddress((void**)&w2c,  g_w2c);
    cudaGetSymbolAddress((void**)&headc, g_headc);

    cudaFuncSetAttribute(flash_attn_kernel,
                         cudaFuncAttributeMaxDynamicSharedMemorySize, FA_SMEM);

    const int D = DMODEL;
    const long DD = (long)D * D;

    // 1) weight prep: LoRA folds + fp16 conversions
    {
        int nblk = (int)(DEPTH * DD / 4 / 256);
        weff_qkv_kernel<<<3 * nblk, 256>>>(Wq, Aq, Bq, Wk, Ak, Bk, Wv, Av, Bv,
                                           wqkv);
        weff_kernel<<<nblk, 256>>>(Wo, Ao, Bo, wo, DD, 0);
        bias_concat_kernel<<<DEPTH * 3 * D / 256, 256>>>(bq, bk, bv, bqkv);
        conv_f16_kernel<<<DEPTH * HIDDEN * D / 1024, 256>>>(W1, w1c);
        conv_f16_kernel<<<DEPTH * HIDDEN * D / 1024, 256>>>(W2, w2c);
        conv_f16_kernel<<<VOCAB * D / 1024, 256>>>(headW, headc);
    }
    embed_kernel<<<NTOK, 256>>>(idx, tok, pos, phase, x);

    // 2) transformer layers
    for (int i = 0; i < DEPTH; i++) {
        const __half* wqkv_i = wqkv + (long)i * 3 * DD;
        const __half* woi    = wo + (long)i * DD;

        ln_kernel<<<NTOK, 256>>>(x, ln1w + i * D, ln1b + i * D, h);

        // fused QKV (fp16 output)
        tgemm(h, D, wqkv_i, D, bqkv + (long)i * 3 * D, nullptr, 0,
              qkv, 3 * D, NTOK, 3 * D, D, /*flags=*/32);

        flash_attn_kernel<<<dim3(SEQL / 128, BATCH * NHEAD), 256, FA_SMEM>>>(
            qkv, o);

        // x = x + o @ Wo_eff^T + bo  (fp32 output + residual)
        tgemm(o, D, woi, D, bo + i * D, x, D, x, D, NTOK, D, D, 0);

        ln_kernel<<<NTOK, 256>>>(x, ln2w + i * D, ln2b + i * D, h);

        // ff = fp16(gelu(h @ W1^T + b1))
        tgemm(h, D, w1c + (long)i * HIDDEN * D, D, b1 + i * HIDDEN,
              nullptr, 0, ff, HIDDEN, NTOK, HIDDEN, D, /*flags=*/1 | 32);
        // x = x + ff @ W2^T + b2
        tgemm(ff, HIDDEN, w2c + (long)i * D * HIDDEN, HIDDEN, b2 + i * D,
              x, D, x, D, NTOK, D, HIDDEN, 0);
    }

    // 3) final LN + LM head (grid-swapped for L2 B reuse)
    ln_kernel<<<NTOK, 256>>>(x, lnfw, lnfb, h);
    tgemm(h, D, headc, D, nullptr, nullptr, 0, out, VOCAB,
          NTOK, VOCAB, D, /*flags=*/16);
}

// round 14
// speedup vs baseline: 1.1968x; 1.1349x over previous
#include <cuda_runtime.h>
#include <cuda_fp16.h>
#include <cstdint>
#include <math.h>

// ---------------- Problem constants ----------------
#define VOCAB 32000
#define DMODEL 1024
#define DEPTH 6
#define NHEAD 16
#define SEQL 1024
#define BATCH 2
#define LRANK 16
#define HIDDEN 4096
#define HEADDIM 64
#define NTOK (BATCH * SEQL)          // 2048
#define SCALING 0.5f                  // 8.0 / 16

// ---------------- Scratch (device globals; no allocation allowed) -------------
static __device__ float  g_x  [NTOK * DMODEL];
static __device__ __half g_h  [NTOK * DMODEL];
static __device__ __half g_qkv[NTOK * 3 * DMODEL];
static __device__ __half g_o  [NTOK * DMODEL];
static __device__ __half g_ff [NTOK * HIDDEN];
static __device__ __half g_wqkv[DEPTH * 3 * DMODEL * DMODEL];
static __device__ float  g_bqkv[DEPTH * 3 * DMODEL];
static __device__ __half g_wo  [DEPTH * DMODEL * DMODEL];
static __device__ __half g_w1c [DEPTH * HIDDEN * DMODEL];
static __device__ __half g_w2c [DEPTH * DMODEL * HIDDEN];
static __device__ __half g_headc[(long)VOCAB * DMODEL];

// ---------------- small PTX helpers (baseline ISA only) ----------------
__device__ __forceinline__ uint32_t smem_u32(const void* p) {
    uint32_t a;
    asm("{ .reg .u64 t; cvta.to.shared.u64 t, %1; cvt.u32.u64 %0, t; }"
        : "=r"(a) : "l"(p));
    return a;
}
__device__ __forceinline__ void cp16(uint32_t dst, const void* src) {
    asm volatile("cp.async.cg.shared.global [%0], [%1], 16;"
                 :: "r"(dst), "l"(src));
}
#define CP_COMMIT() asm volatile("cp.async.commit_group;" ::: "memory")
#define CP_WAIT1()  asm volatile("cp.async.wait_group 1;"  ::: "memory")
#define CP_WAIT0()  asm volatile("cp.async.wait_group 0;"  ::: "memory")

// fp16 MMA: m16n8k16, fp32 accumulate
__device__ __forceinline__ void mma_f16(float* d, const uint32_t* a,
                                        const uint32_t* b) {
    asm volatile(
        "mma.sync.aligned.m16n8k16.row.col.f32.f16.f16.f32 "
        "{%0,%1,%2,%3}, {%4,%5,%6,%7}, {%8,%9}, {%0,%1,%2,%3};"
        : "+f"(d[0]), "+f"(d[1]), "+f"(d[2]), "+f"(d[3])
        : "r"(a[0]), "r"(a[1]), "r"(a[2]), "r"(a[3]), "r"(b[0]), "r"(b[1]));
}

// ldmatrix x4: loads 4 8x8 fp16 matrices; per-thread address = one 16B row
__device__ __forceinline__ void ldsm_x4(uint32_t* r, uint32_t addr) {
    asm volatile("ldmatrix.sync.aligned.m8n8.x4.shared.b16 {%0,%1,%2,%3}, [%4];"
                 : "=r"(r[0]), "=r"(r[1]), "=r"(r[2]), "=r"(r[3])
                 : "r"(addr));
}
// transposed variant: returns transposes of the 4 source 8x8 tiles
__device__ __forceinline__ void ldsm_x4_t(uint32_t* r, uint32_t addr) {
    asm volatile("ldmatrix.sync.aligned.m8n8.x4.trans.shared.b16 {%0,%1,%2,%3}, [%4];"
                 : "=r"(r[0]), "=r"(r[1]), "=r"(r[2]), "=r"(r[3])
                 : "r"(addr));
}

// ---------------- helpers ----------------
__device__ __forceinline__ float gelu_exact(float x) {
    return 0.5f * x * (1.0f + erff(x * 0.70710678118654752440f));
}
__device__ __forceinline__ uint32_t pack_h2(float a, float b) {
    __half2 h = __floats2half2_rn(a, b);
    return *reinterpret_cast<uint32_t*>(&h);
}

// ---------------- fp16 round-copy (for W1/W2/headW) ----------------
__global__ void conv_f16_kernel(const float* __restrict__ src,
                                __half* __restrict__ dst) {
    long e4 = ((long)blockIdx.x * 256 + threadIdx.x) * 4;
    float4 f = *reinterpret_cast<const float4*>(src + e4);
    uint2 u;
    u.x = pack_h2(f.x, f.y);
    u.y = pack_h2(f.z, f.w);
    *reinterpret_cast<uint2*>(dst + e4) = u;
}

// ---------------- LoRA fold body (writes fp16) ----------------
__device__ __forceinline__ void weff_body(long e4,
                                          const float* __restrict__ W,
                                          const float* __restrict__ Am,
                                          const float* __restrict__ Bm,
                                          __half* __restrict__ out,
                                          long outLS, long outOff) {
    const int DD4 = DMODEL * DMODEL / 4;
    int layer = (int)(e4 / DD4);
    int rem4  = (int)(e4 % DD4);
    int orow  = rem4 / (DMODEL / 4);
    int ic4   = (rem4 % (DMODEL / 4)) * 4;
    const float* a  = Am + (long)layer * DMODEL * LRANK + (long)orow * LRANK;
    const float* bb = Bm + (long)layer * LRANK * DMODEL + ic4;
    float4 s = make_float4(0.f, 0.f, 0.f, 0.f);
#pragma unroll
    for (int r = 0; r < LRANK; r++) {
        float4 bv = *reinterpret_cast<const float4*>(bb + (long)r * DMODEL);
        float av = a[r];
        s.x += av * bv.x; s.y += av * bv.y; s.z += av * bv.z; s.w += av * bv.w;
    }
    float4 wv = *reinterpret_cast<const float4*>(
        W + (long)layer * DMODEL * DMODEL + rem4 * 4);
    uint2 u;
    u.x = pack_h2(wv.x + SCALING * s.x, wv.y + SCALING * s.y);
    u.y = pack_h2(wv.z + SCALING * s.z, wv.w + SCALING * s.w);
    *reinterpret_cast<uint2*>(out + (long)layer * outLS + outOff + rem4 * 4) = u;
}

__global__ void weff_qkv_kernel(const float* __restrict__ Wq, const float* __restrict__ Aq, const float* __restrict__ Bq,
                                const float* __restrict__ Wk, const float* __restrict__ Ak, const float* __restrict__ Bk,
                                const float* __restrict__ Wv, const float* __restrict__ Av, const float* __restrict__ Bv,
                                __half* __restrict__ out) {
    const int nblk = DEPTH * DMODEL * DMODEL / 4 / 256;
    int seg = blockIdx.x / nblk;
    long e4 = (long)(blockIdx.x % nblk) * 256 + threadIdx.x;
    const long DD = (long)DMODEL * DMODEL;
    const float *W = (seg == 0) ? Wq : (seg == 1 ? Wk : Wv);
    const float *A = (seg == 0) ? Aq : (seg == 1 ? Ak : Av);
    const float *B = (seg == 0) ? Bq : (seg == 1 ? Bk : Bv);
    weff_body(e4, W, A, B, out, 3 * DD, seg * DD);
}

__global__ void weff_kernel(const float* __restrict__ W,
                            const float* __restrict__ Am,
                            const float* __restrict__ Bm,
                            __half* __restrict__ out,
                            long outLS, long outOff) {
    long e4 = (long)blockIdx.x * 256 + threadIdx.x;
    weff_body(e4, W, Am, Bm, out, outLS, outOff);
}

// ---------------- bias concat for fused QKV ----------------
__global__ void bias_concat_kernel(const float* __restrict__ bq,
                                   const float* __restrict__ bk,
                                   const float* __restrict__ bv,
                                   float* __restrict__ out) {
    int e = blockIdx.x * 256 + threadIdx.x;
    int layer = e / (3 * DMODEL);
    int r = e % (3 * DMODEL);
    const float* src = (r < DMODEL) ? bq : (r < 2 * DMODEL ? bk : bv);
    out[e] = src[layer * DMODEL + (r % DMODEL)];
}

// ---------------- Embedding + phase rotator (x stays fp32) ----------------
__global__ void embed_kernel(const int* __restrict__ idx,
                             const float* __restrict__ tok,
                             const float* __restrict__ pos,
                             const float* __restrict__ phase,
                             float* __restrict__ x) {
    int row = blockIdx.x;
    int l   = row % SEQL;
    int t   = idx[row];
    for (int d = threadIdx.x; d < DMODEL; d += blockDim.x) {
        float phi = tanhf(phase[d]) * 3.14159265358979323846f;
        float fac = cosf(phi) - sinf(phi);
        x[(long)row * DMODEL + d] =
            (tok[(long)t * DMODEL + d] + pos[(long)l * DMODEL + d]) * fac;
    }
}

// ---------------- LayerNorm (fp32 in, fp16 out) ----------------
__global__ void ln_kernel(const float* __restrict__ x,
                          const float* __restrict__ w,
                          const float* __restrict__ b,
                          __half* __restrict__ o) {
    int row = blockIdx.x;
    const float* xr = x + (long)row * DMODEL;
    int tid = threadIdx.x;
    float s = 0.f, s2 = 0.f;
    float v[4];
#pragma unroll
    for (int j = 0; j < 4; j++) {
        v[j] = xr[tid + 256 * j];
        s += v[j]; s2 += v[j] * v[j];
    }
    __shared__ float r1[256], r2[256];
    r1[tid] = s; r2[tid] = s2;
    __syncthreads();
    for (int off = 128; off > 0; off >>= 1) {
        if (tid < off) { r1[tid] += r1[tid + off]; r2[tid] += r2[tid + off]; }
        __syncthreads();
    }
    float mean = r1[0] * (1.0f / DMODEL);
    float var  = r2[0] * (1.0f / DMODEL) - mean * mean;
    float rstd = rsqrtf(var + 1e-5f);
    __half* orow = o + (long)row * DMODEL;
#pragma unroll
    for (int j = 0; j < 4; j++) {
        int d = tid + 256 * j;
        orow[d] = __float2half_rn((v[j] - mean) * rstd * w[d] + b[d]);
    }
}

// ---------------- Fused flash attention (fp16 MMA + ldmatrix[.trans]) -------
// grid: (8 q-tiles, 32 batch-heads), 256 threads (8 warps x 16 q-rows).
// V^T fragments come straight from row-major Vraw via ldmatrix.trans —
// no SMEM transpose pass.
static constexpr int FA_K_OFF  = 0;
static constexpr int FA_V_OFF  = 128 * 72;
static constexpr int FA_P_OFF  = 2 * 128 * 72;
static constexpr int FA_HALVES = FA_P_OFF + 128 * 136;
static constexpr int FA_SMEM   = FA_HALVES * 2;                   // 71680 B

__global__ __launch_bounds__(256)
void flash_attn_kernel(const __half* __restrict__ qkv, __half* __restrict__ o) {
    extern __shared__ __half fh[];
    __half* Kt   = fh + FA_K_OFF;
    __half* Vraw = fh + FA_V_OFF;
    __half* Pu   = fh + FA_P_OFF;
    __half* Qs   = Pu;                     // Q staging reuses P region

    const int qt = blockIdx.x;
    const int bh = blockIdx.y;
    const int b  = bh >> 4;
    const int h  = bh & 15;

    const int tid  = threadIdx.x;
    const int wid  = tid >> 5;
    const int lane = tid & 31;
    const int g = lane >> 2, tig = lane & 3;

    const int lrow  = lane & 7;
    const int a_row = ((lane >> 3) & 1) * 8;
    const int a_k   = (lane >> 4) * 8;
    const int b_row = (lane >> 4) * 8;
    const int b_k   = ((lane >> 3) & 1) * 8;

    const __half* base = qkv + ((long)b * SEQL) * (3 * DMODEL) + h * HEADDIM;

    // ---- stage Q tile
    {
        int r = tid >> 1, hp = tid & 1;
        const __half* src = base + (long)(qt * 128 + r) * (3 * DMODEL) + hp * 32;
        uint32_t dst = smem_u32(&Qs[r * 72 + hp * 32]);
#pragma unroll
        for (int i = 0; i < 4; i++) cp16(dst + i * 16, src + i * 8);
    }
    CP_COMMIT(); CP_WAIT0(); __syncthreads();

    const __half2 qscale = __floats2half2_rn(0.125f, 0.125f);
    uint32_t qf[4][4];
    {
        uint32_t qbase = smem_u32(Qs) +
            ((wid * 16 + a_row + lrow) * 72 + a_k) * 2;
#pragma unroll
        for (int ks = 0; ks < 4; ks++) {
            uint32_t r[4];
            ldsm_x4(r, qbase + ks * 32);
#pragma unroll
            for (int z = 0; z < 4; z++) {
                __half2 hv = __hmul2(*(__half2*)&r[z], qscale);
                qf[ks][z] = *(uint32_t*)&hv;
            }
        }
    }
    __syncthreads();

    float mold0 = -INFINITY, mold1 = -INFINITY;
    float l0 = 0.f, l1 = 0.f;
    float oacc[8][4];
#pragma unroll
    for (int n = 0; n < 8; n++)
#pragma unroll
        for (int r = 0; r < 4; r++) oacc[n][r] = 0.f;

    const uint32_t kt_b_base = smem_u32(Kt) + ((b_row + lrow) * 72 + b_k) * 2;
    // trans B fragments for P@V: source row = key = b_k + lrow, col = d = b_row
    const uint32_t v_bt_base = smem_u32(Vraw) + ((b_k + lrow) * 72 + b_row) * 2;
    const uint32_t pu_a_base = smem_u32(Pu) +
        ((wid * 16 + a_row + lrow) * 136 + a_k) * 2;

    for (int kt = 0; kt <= qt; kt++) {
        {
            int r = tid >> 1, hp = tid & 1;
            const __half* ksrc = base + (long)(kt * 128 + r) * (3 * DMODEL) + DMODEL + hp * 32;
            const __half* vsrc = base + (long)(kt * 128 + r) * (3 * DMODEL) + 2 * DMODEL + hp * 32;
            uint32_t kd = smem_u32(&Kt[r * 72 + hp * 32]);
            uint32_t vd = smem_u32(&Vraw[r * 72 + hp * 32]);
#pragma unroll
            for (int i = 0; i < 4; i++) cp16(kd + i * 16, ksrc + i * 8);
#pragma unroll
            for (int i = 0; i < 4; i++) cp16(vd + i * 16, vsrc + i * 8);
        }
        CP_COMMIT(); CP_WAIT0(); __syncthreads();

        float sacc[16][4];
#pragma unroll
        for (int n = 0; n < 16; n++)
#pragma unroll
            for (int r = 0; r < 4; r++) sacc[n][r] = 0.f;
#pragma unroll
        for (int ntp = 0; ntp < 8; ntp++) {
            uint32_t baddr = kt_b_base + ntp * (16 * 72 * 2);
#pragma unroll
            for (int ks = 0; ks < 4; ks++) {
                uint32_t r[4];
                ldsm_x4(r, baddr + ks * 32);
                mma_f16(sacc[2 * ntp    ], qf[ks], r);
                mma_f16(sacc[2 * ntp + 1], qf[ks], r + 2);
            }
        }

        if (kt == qt) {
            int r0 = wid * 16 + g, r1 = r0 + 8;
#pragma unroll
            for (int nt = 0; nt < 16; nt++) {
                int c0 = nt * 8 + tig * 2;
                if (c0     > r0) sacc[nt][0] = -INFINITY;
                if (c0 + 1 > r0) sacc[nt][1] = -INFINITY;
                if (c0     > r1) sacc[nt][2] = -INFINITY;
                if (c0 + 1 > r1) sacc[nt][3] = -INFINITY;
            }
        }

        float tm0 = -INFINITY, tm1 = -INFINITY;
#pragma unroll
        for (int nt = 0; nt < 16; nt++) {
            tm0 = fmaxf(tm0, fmaxf(sacc[nt][0], sacc[nt][1]));
            tm1 = fmaxf(tm1, fmaxf(sacc[nt][2], sacc[nt][3]));
        }
        tm0 = fmaxf(tm0, __shfl_xor_sync(0xffffffffu, tm0, 1));
        tm0 = fmaxf(tm0, __shfl_xor_sync(0xffffffffu, tm0, 2));
        tm1 = fmaxf(tm1, __shfl_xor_sync(0xffffffffu, tm1, 1));
        tm1 = fmaxf(tm1, __shfl_xor_sync(0xffffffffu, tm1, 2));
        float mn0 = fmaxf(mold0, tm0), mn1 = fmaxf(mold1, tm1);
        float a0 = __expf(mold0 - mn0), a1 = __expf(mold1 - mn1);

        float sum0 = 0.f, sum1 = 0.f;
        int prow = wid * 16 + g;
        uint32_t* Pw = (uint32_t*)Pu;
#pragma unroll
        for (int nt = 0; nt < 16; nt++) {
            float p0 = __expf(sacc[nt][0] - mn0);
            float p1 = __expf(sacc[nt][1] - mn0);
            float p2 = __expf(sacc[nt][2] - mn1);
            float p3 = __expf(sacc[nt][3] - mn1);
            sum0 += p0 + p1; sum1 += p2 + p3;
            int c = nt * 4 + tig;
            Pw[(prow    ) * 68 + c] = pack_h2(p0, p1);
            Pw[(prow + 8) * 68 + c] = pack_h2(p2, p3);
        }
        sum0 += __shfl_xor_sync(0xffffffffu, sum0, 1);
        sum0 += __shfl_xor_sync(0xffffffffu, sum0, 2);
        sum1 += __shfl_xor_sync(0xffffffffu, sum1, 1);
        sum1 += __shfl_xor_sync(0xffffffffu, sum1, 2);
        l0 = l0 * a0 + sum0;
        l1 = l1 * a1 + sum1;
#pragma unroll
        for (int nt = 0; nt < 8; nt++) {
            oacc[nt][0] *= a0; oacc[nt][1] *= a0;
            oacc[nt][2] *= a1; oacc[nt][3] *= a1;
        }
        mold0 = mn0; mold1 = mn1;
        __syncthreads();

        // ---- O += P @ V  (A from Pu; B = V^T tiles via ldmatrix.trans)
#pragma unroll
        for (int ks = 0; ks < 8; ks++) {
            uint32_t af[4];
            ldsm_x4(af, pu_a_base + ks * 32);
            uint32_t vb = v_bt_base + ks * (16 * 72 * 2);
#pragma unroll
            for (int ntp = 0; ntp < 4; ntp++) {
                uint32_t r[4];
                ldsm_x4_t(r, vb + ntp * 32);
                mma_f16(oacc[2 * ntp    ], af, r);
                mma_f16(oacc[2 * ntp + 1], af, r + 2);
            }
        }
        __syncthreads();
    }

    float i0 = 1.0f / l0, i1 = 1.0f / l1;
    int tok = b * SEQL + qt * 128 + wid * 16 + g;
    __half* o0 = o + (long)tok * DMODEL + h * HEADDIM;
    __half* o1 = o0 + 8 * DMODEL;
#pragma unroll
    for (int nt = 0; nt < 8; nt++) {
        int c = nt * 8 + tig * 2;
        *(uint32_t*)&o0[c] = pack_h2(oacc[nt][0] * i0, oacc[nt][1] * i0);
        *(uint32_t*)&o1[c] = pack_h2(oacc[nt][2] * i1, oacc[nt][3] * i1);
    }
}

// ---------------- fp16 mma.sync GEMM (2-stage + ldmatrix, BK=64) ------------
// C[m,n] = sum_k A[m*lda+k] * B[n*sBn+k]  (+bias)(gelu); out fp32(+res) or fp16
// flags: 1 = gelu, 16 = grid swap, 32 = fp16 output
// BM=128, BN=128, BK=64 halves; 8 warps 2x4; warp tile 64x32.
__global__ __launch_bounds__(256)
void mma_gemm(const __half* __restrict__ A, int lda,
              const __half* __restrict__ Bp, long sBn,
              const float* __restrict__ bias,
              const float* __restrict__ res, int ldr,
              void* __restrict__ Cv, int ldc,
              int K, int flags) {
    constexpr int BM = 128, BN = 128, BK = 64, LDSH = BK + 8;   // 72 halves/row
    extern __shared__ __half smh[];
    __half* As = smh;                         // [2][BM][72]
    __half* Bs = smh + 2 * BM * LDSH;         // [2][BN][72]

    int bx = blockIdx.x, by = blockIdx.y;
    if (flags & 16) { int t = bx; bx = by; by = t; }
    const int bm0 = by * BM;
    const int bn0 = bx * BN;
    const int T = K / BK;

    const int tid  = threadIdx.x;
    const int w    = tid >> 5;
    const int lane = tid & 31;
    const int wm = w >> 2, wn = w & 3;
    const int g = lane >> 2, tig = lane & 3;

    const int lrow  = lane & 7;
    const int a_row = ((lane >> 3) & 1) * 8;
    const int a_k   = (lane >> 4) * 8;
    const int b_row = (lane >> 4) * 8;
    const int b_k   = ((lane >> 3) & 1) * 8;

    const uint32_t a_base = smem_u32(As) +
        ((wm * 64 + a_row + lrow) * LDSH + a_k) * 2;
    const uint32_t b_base = smem_u32(Bs) +
        ((wn * 32 + b_row + lrow) * LDSH + b_k) * 2;
    constexpr uint32_t ABUF = BM * LDSH * 2;
    constexpr uint32_t BBUF = BN * LDSH * 2;

    float acc[4][4][4];
#pragma unroll
    for (int i = 0; i < 4; i++)
#pragma unroll
        for (int j = 0; j < 4; j++)
#pragma unroll
            for (int r = 0; r < 4; r++) acc[i][j][r] = 0.0f;

    auto load_tile = [&](int it, int buf) {
        const int k0 = it * BK;
        // 128 rows x 64 halves = 8 chunks/row of 8 halves; 4 cp16/thread each
#pragma unroll
        for (int t = 0; t < 4; t++) {
            int vv = tid + t * 256;
            int m = vv >> 3, c = vv & 7;
            cp16(smem_u32(&As[(buf * BM + m) * LDSH + c * 8]),
                 A + (long)(bm0 + m) * lda + k0 + c * 8);
        }
#pragma unroll
        for (int t = 0; t < 4; t++) {
            int vv = tid + t * 256;
            int n = vv >> 3, c = vv & 7;
            cp16(smem_u32(&Bs[(buf * BN + n) * LDSH + c * 8]),
                 Bp + (long)(bn0 + n) * sBn + k0 + c * 8);
        }
    };

    load_tile(0, 0);
    CP_COMMIT();

    for (int it = 0; it < T; it++) {
        const int buf = it & 1;
        if (it + 1 < T) {
            load_tile(it + 1, buf ^ 1);
            CP_COMMIT();
            CP_WAIT1();
        } else {
            CP_WAIT0();
        }
        __syncthreads();

        const uint32_t ab = a_base + buf * ABUF;
        const uint32_t bb = b_base + buf * BBUF;

#pragma unroll
        for (int ks = 0; ks < 4; ks++) {       // 4 k16-steps per BK=64
            uint32_t af[4][4];
#pragma unroll
            for (int i = 0; i < 4; i++)
                ldsm_x4(af[i], ab + i * (16 * LDSH * 2) + ks * 32);
            uint32_t bf[4][4];                  // 2 ldmatrix cover 4 n8 tiles
            ldsm_x4(bf[0], bb + ks * 32);
            ldsm_x4(bf[2], bb + 16 * LDSH * 2 + ks * 32);
#pragma unroll
            for (int i = 0; i < 4; i++) {
                mma_f16(acc[i][0], af[i], bf[0]);
                mma_f16(acc[i][1], af[i], bf[0] + 2);
                mma_f16(acc[i][2], af[i], bf[2]);
                mma_f16(acc[i][3], af[i], bf[2] + 2);
            }
        }
        __syncthreads();
    }

    // epilogue -----------------------------------------------------------
#pragma unroll
    for (int i = 0; i < 4; i++) {
        int r0 = bm0 + wm * 64 + i * 16 + g;
#pragma unroll
        for (int j = 0; j < 4; j++) {
            int c = bn0 + wn * 32 + j * 8 + tig * 2;
            float e00 = acc[i][j][0], e01 = acc[i][j][1];
            float e10 = acc[i][j][2], e11 = acc[i][j][3];
            if (bias) {
                float2 bb2 = *reinterpret_cast<const float2*>(bias + c);
                e00 += bb2.x; e01 += bb2.y; e10 += bb2.x; e11 += bb2.y;
            }
            if (flags & 1) {
                e00 = gelu_exact(e00); e01 = gelu_exact(e01);
                e10 = gelu_exact(e10); e11 = gelu_exact(e11);
            }
            if (flags & 32) {
                __half* C = (__half*)Cv;
                *(uint32_t*)&C[(long)r0 * ldc + c]       = pack_h2(e00, e01);
                *(uint32_t*)&C[(long)(r0 + 8) * ldc + c] = pack_h2(e10, e11);
            } else {
                float* C = (float*)Cv;
                if (res) {
                    float2 ra = *reinterpret_cast<const float2*>(
                        res + (long)r0 * ldr + c);
                    float2 rb = *reinterpret_cast<const float2*>(
                        res + (long)(r0 + 8) * ldr + c);
                    e00 += ra.x; e01 += ra.y; e10 += rb.x; e11 += rb.y;
                }
                *reinterpret_cast<float2*>(C + (long)r0 * ldc + c) =
                    make_float2(e00, e01);
                *reinterpret_cast<float2*>(C + (long)(r0 + 8) * ldc + c) =
                    make_float2(e10, e11);
            }
        }
    }
}

// ---------------- host-side launch helper ----------------
static constexpr int GEMM_SMEM = (2 * 128 * 72 + 2 * 128 * 72) * 2;  // 73728

static void tgemm(const __half* A, int lda, const __half* B, long sBn,
                  const float* bias, const float* res, int ldr,
                  void* C, int ldc, int M, int N, int K, int flags) {
    dim3 gdim;
    if (flags & 16) gdim = dim3(M / 128, N / 128, 1);
    else            gdim = dim3(N / 128, M / 128, 1);
    mma_gemm<<<gdim, 256, GEMM_SMEM>>>(A, lda, B, sBn, bias, res, ldr,
                                       C, ldc, K, flags);
}

// ---------------- entry point ----------------
extern "C" void kernel_launch(void* const* d_in, const int* in_sizes, int n_in,
                              void* d_out, int out_size) {
    const int*   idx   = (const int*)  d_in[0];
    const float* tok   = (const float*)d_in[1];
    const float* pos   = (const float*)d_in[2];
    const float* phase = (const float*)d_in[3];
    const float* ln1w  = (const float*)d_in[4];
    const float* ln1b  = (const float*)d_in[5];

    const float *ln2w, *ln2b;
    int wbase;
    if (in_sizes[6] == DEPTH * DMODEL) {        // dict order
        ln2w = (const float*)d_in[6];
        ln2b = (const float*)d_in[7];
        wbase = 8;
    } else {                                     // signature order fallback
        ln2w = (const float*)d_in[22];
        ln2b = (const float*)d_in[23];
        wbase = 6;
    }
    const float* Wq = (const float*)d_in[wbase + 0];
    const float* bq = (const float*)d_in[wbase + 1];
    const float* Bq = (const float*)d_in[wbase + 2];
    const float* Aq = (const float*)d_in[wbase + 3];
    const float* Wk = (const float*)d_in[wbase + 4];
    const float* bk = (const float*)d_in[wbase + 5];
    const float* Bk = (const float*)d_in[wbase + 6];
    const float* Ak = (const float*)d_in[wbase + 7];
    const float* Wv = (const float*)d_in[wbase + 8];
    const float* bv = (const float*)d_in[wbase + 9];
    const float* Bv = (const float*)d_in[wbase + 10];
    const float* Av = (const float*)d_in[wbase + 11];
    const float* Wo = (const float*)d_in[wbase + 12];
    const float* bo = (const float*)d_in[wbase + 13];
    const float* Bo = (const float*)d_in[wbase + 14];
    const float* Ao = (const float*)d_in[wbase + 15];
    const float* W1 = (const float*)d_in[24];
    const float* b1 = (const float*)d_in[25];
    const float* W2 = (const float*)d_in[26];
    const float* b2 = (const float*)d_in[27];
    const float* lnfw = (const float*)d_in[28];
    const float* lnfb = (const float*)d_in[29];
    const float* headW = (const float*)d_in[30];
    float* out = (float*)d_out;

    float *x, *bqkv;
    __half *h, *qkv, *o, *ff, *wqkv, *wo, *w1c, *w2c, *headc;
    cudaGetSymbolAddress((void**)&x,    g_x);
    cudaGetSymbolAddress((void**)&h,    g_h);
    cudaGetSymbolAddress((void**)&qkv,  g_qkv);
    cudaGetSymbolAddress((void**)&o,    g_o);
    cudaGetSymbolAddress((void**)&ff,   g_ff);
    cudaGetSymbolAddress((void**)&wqkv, g_wqkv);
    cudaGetSymbolAddress((void**)&bqkv, g_bqkv);
    cudaGetSymbolAddress((void**)&wo,   g_wo);
    cudaGetSymbolAddress((void**)&w1c,  g_w1c);
    cudaGetSymbolAddress((void**)&w2c,  g_w2c);
    cudaGetSymbolAddress((void**)&headc, g_headc);

    cudaFuncSetAttribute(flash_attn_kernel,
                         cudaFuncAttributeMaxDynamicSharedMemorySize, FA_SMEM);
    cudaFuncSetAttribute(mma_gemm,
                         cudaFuncAttributeMaxDynamicSharedMemorySize, GEMM_SMEM);

    const int D = DMODEL;
    const long DD = (long)D * D;

    // 1) weight prep: LoRA folds + fp16 conversions
    {
        int nblk = (int)(DEPTH * DD / 4 / 256);
        weff_qkv_kernel<<<3 * nblk, 256>>>(Wq, Aq, Bq, Wk, Ak, Bk, Wv, Av, Bv,
                                           wqkv);
        weff_kernel<<<nblk, 256>>>(Wo, Ao, Bo, wo, DD, 0);
        bias_concat_kernel<<<DEPTH * 3 * D / 256, 256>>>(bq, bk, bv, bqkv);
        conv_f16_kernel<<<DEPTH * HIDDEN * D / 1024, 256>>>(W1, w1c);
        conv_f16_kernel<<<DEPTH * HIDDEN * D / 1024, 256>>>(W2, w2c);
        conv_f16_kernel<<<VOCAB * D / 1024, 256>>>(headW, headc);
    }
    embed_kernel<<<NTOK, 256>>>(idx, tok, pos, phase, x);

    // 2) transformer layers
    for (int i = 0; i < DEPTH; i++) {
        const __half* wqkv_i = wqkv + (long)i * 3 * DD;
        const __half* woi    = wo + (long)i * DD;

        ln_kernel<<<NTOK, 256>>>(x, ln1w + i * D, ln1b + i * D, h);

        // fused QKV (fp16 output)
        tgemm(h, D, wqkv_i, D, bqkv + (long)i * 3 * D, nullptr, 0,
              qkv, 3 * D, NTOK, 3 * D, D, /*flags=*/32);

        flash_attn_kernel<<<dim3(SEQL / 128, BATCH * NHEAD), 256, FA_SMEM>>>(
            qkv, o);

        // x = x + o @ Wo_eff^T + bo  (fp32 output + residual)
        tgemm(o, D, woi, D, bo + i * D, x, D, x, D, NTOK, D, D, 0);

        ln_kernel<<<NTOK, 256>>>(x, ln2w + i * D, ln2b + i * D, h);

        // ff = fp16(gelu(h @ W1^T + b1))
        tgemm(h, D, w1c + (long)i * HIDDEN * D, D, b1 + i * HIDDEN,
              nullptr, 0, ff, HIDDEN, NTOK, HIDDEN, D, /*flags=*/1 | 32);
        // x = x + ff @ W2^T + b2
        tgemm(ff, HIDDEN, w2c + (long)i * D * HIDDEN, HIDDEN, b2 + i * D,
              x, D, x, D, NTOK, D, HIDDEN, 0);
    }

    // 3) final LN + LM head (grid-swapped for L2 B reuse)
    ln_kernel<<<NTOK, 256>>>(x, lnfw, lnfb, h);
    tgemm(h, D, headc, D, nullptr, nullptr, 0, out, VOCAB,
          NTOK, VOCAB, D, /*flags=*/16);
}

// round 15
// speedup vs baseline: 1.2245x; 1.0232x over previous
#include <cuda_runtime.h>
#include <cuda_fp16.h>
#include <cstdint>
#include <math.h>

// ---------------- Problem constants ----------------
#define VOCAB 32000
#define DMODEL 1024
#define DEPTH 6
#define NHEAD 16
#define SEQL 1024
#define BATCH 2
#define LRANK 16
#define HIDDEN 4096
#define HEADDIM 64
#define NTOK (BATCH * SEQL)          // 2048
#define SCALING 0.5f                  // 8.0 / 16

// ---------------- Scratch (device globals; no allocation allowed) -------------
static __device__ float  g_x  [NTOK * DMODEL];
static __device__ __half g_h  [NTOK * DMODEL];
static __device__ __half g_qkv[NTOK * 3 * DMODEL];
static __device__ __half g_o  [NTOK * DMODEL];
static __device__ __half g_ff [NTOK * HIDDEN];
static __device__ __half g_wqkv[DEPTH * 3 * DMODEL * DMODEL];
static __device__ float  g_bqkv[DEPTH * 3 * DMODEL];
static __device__ __half g_wo  [DEPTH * DMODEL * DMODEL];
static __device__ __half g_w1c [DEPTH * HIDDEN * DMODEL];
static __device__ __half g_w2c [DEPTH * DMODEL * HIDDEN];
static __device__ __half g_headc[(long)VOCAB * DMODEL];

// ---------------- small PTX helpers (baseline ISA only) ----------------
__device__ __forceinline__ uint32_t smem_u32(const void* p) {
    uint32_t a;
    asm("{ .reg .u64 t; cvta.to.shared.u64 t, %1; cvt.u32.u64 %0, t; }"
        : "=r"(a) : "l"(p));
    return a;
}
__device__ __forceinline__ void cp16(uint32_t dst, const void* src) {
    asm volatile("cp.async.cg.shared.global [%0], [%1], 16;"
                 :: "r"(dst), "l"(src));
}
#define CP_COMMIT() asm volatile("cp.async.commit_group;" ::: "memory")
#define CP_WAIT1()  asm volatile("cp.async.wait_group 1;"  ::: "memory")
#define CP_WAIT0()  asm volatile("cp.async.wait_group 0;"  ::: "memory")

// fp16 MMA: m16n8k16, fp32 accumulate
__device__ __forceinline__ void mma_f16(float* d, const uint32_t* a,
                                        const uint32_t* b) {
    asm volatile(
        "mma.sync.aligned.m16n8k16.row.col.f32.f16.f16.f32 "
        "{%0,%1,%2,%3}, {%4,%5,%6,%7}, {%8,%9}, {%0,%1,%2,%3};"
        : "+f"(d[0]), "+f"(d[1]), "+f"(d[2]), "+f"(d[3])
        : "r"(a[0]), "r"(a[1]), "r"(a[2]), "r"(a[3]), "r"(b[0]), "r"(b[1]));
}

// ldmatrix x4: loads 4 8x8 fp16 matrices; per-thread address = one 16B row
__device__ __forceinline__ void ldsm_x4(uint32_t* r, uint32_t addr) {
    asm volatile("ldmatrix.sync.aligned.m8n8.x4.shared.b16 {%0,%1,%2,%3}, [%4];"
                 : "=r"(r[0]), "=r"(r[1]), "=r"(r[2]), "=r"(r[3])
                 : "r"(addr));
}
// transposed variant: returns transposes of the 4 source 8x8 tiles
__device__ __forceinline__ void ldsm_x4_t(uint32_t* r, uint32_t addr) {
    asm volatile("ldmatrix.sync.aligned.m8n8.x4.trans.shared.b16 {%0,%1,%2,%3}, [%4];"
                 : "=r"(r[0]), "=r"(r[1]), "=r"(r[2]), "=r"(r[3])
                 : "r"(addr));
}

// ---------------- helpers ----------------
__device__ __forceinline__ float gelu_exact(float x) {
    return 0.5f * x * (1.0f + erff(x * 0.70710678118654752440f));
}
__device__ __forceinline__ uint32_t pack_h2(float a, float b) {
    __half2 h = __floats2half2_rn(a, b);
    return *reinterpret_cast<uint32_t*>(&h);
}

// ---------------- fp16 round-copy (for W1/W2/headW) ----------------
__global__ void conv_f16_kernel(const float* __restrict__ src,
                                __half* __restrict__ dst) {
    long e4 = ((long)blockIdx.x * 256 + threadIdx.x) * 4;
    float4 f = *reinterpret_cast<const float4*>(src + e4);
    uint2 u;
    u.x = pack_h2(f.x, f.y);
    u.y = pack_h2(f.z, f.w);
    *reinterpret_cast<uint2*>(dst + e4) = u;
}

// ---------------- LoRA fold body (writes fp16) ----------------
__device__ __forceinline__ void weff_body(long e4,
                                          const float* __restrict__ W,
                                          const float* __restrict__ Am,
                                          const float* __restrict__ Bm,
                                          __half* __restrict__ out,
                                          long outLS, long outOff) {
    const int DD4 = DMODEL * DMODEL / 4;
    int layer = (int)(e4 / DD4);
    int rem4  = (int)(e4 % DD4);
    int orow  = rem4 / (DMODEL / 4);
    int ic4   = (rem4 % (DMODEL / 4)) * 4;
    const float* a  = Am + (long)layer * DMODEL * LRANK + (long)orow * LRANK;
    const float* bb = Bm + (long)layer * LRANK * DMODEL + ic4;
    float4 s = make_float4(0.f, 0.f, 0.f, 0.f);
#pragma unroll
    for (int r = 0; r < LRANK; r++) {
        float4 bv = *reinterpret_cast<const float4*>(bb + (long)r * DMODEL);
        float av = a[r];
        s.x += av * bv.x; s.y += av * bv.y; s.z += av * bv.z; s.w += av * bv.w;
    }
    float4 wv = *reinterpret_cast<const float4*>(
        W + (long)layer * DMODEL * DMODEL + rem4 * 4);
    uint2 u;
    u.x = pack_h2(wv.x + SCALING * s.x, wv.y + SCALING * s.y);
    u.y = pack_h2(wv.z + SCALING * s.z, wv.w + SCALING * s.w);
    *reinterpret_cast<uint2*>(out + (long)layer * outLS + outOff + rem4 * 4) = u;
}

__global__ void weff_qkv_kernel(const float* __restrict__ Wq, const float* __restrict__ Aq, const float* __restrict__ Bq,
                                const float* __restrict__ Wk, const float* __restrict__ Ak, const float* __restrict__ Bk,
                                const float* __restrict__ Wv, const float* __restrict__ Av, const float* __restrict__ Bv,
                                __half* __restrict__ out) {
    const int nblk = DEPTH * DMODEL * DMODEL / 4 / 256;
    int seg = blockIdx.x / nblk;
    long e4 = (long)(blockIdx.x % nblk) * 256 + threadIdx.x;
    const long DD = (long)DMODEL * DMODEL;
    const float *W = (seg == 0) ? Wq : (seg == 1 ? Wk : Wv);
    const float *A = (seg == 0) ? Aq : (seg == 1 ? Ak : Av);
    const float *B = (seg == 0) ? Bq : (seg == 1 ? Bk : Bv);
    weff_body(e4, W, A, B, out, 3 * DD, seg * DD);
}

__global__ void weff_kernel(const float* __restrict__ W,
                            const float* __restrict__ Am,
                            const float* __restrict__ Bm,
                            __half* __restrict__ out,
                            long outLS, long outOff) {
    long e4 = (long)blockIdx.x * 256 + threadIdx.x;
    weff_body(e4, W, Am, Bm, out, outLS, outOff);
}

// ---------------- bias concat for fused QKV ----------------
__global__ void bias_concat_kernel(const float* __restrict__ bq,
                                   const float* __restrict__ bk,
                                   const float* __restrict__ bv,
                                   float* __restrict__ out) {
    int e = blockIdx.x * 256 + threadIdx.x;
    int layer = e / (3 * DMODEL);
    int r = e % (3 * DMODEL);
    const float* src = (r < DMODEL) ? bq : (r < 2 * DMODEL ? bk : bv);
    out[e] = src[layer * DMODEL + (r % DMODEL)];
}

// ---------------- Embedding + phase rotator (x stays fp32) ----------------
__global__ void embed_kernel(const int* __restrict__ idx,
                             const float* __restrict__ tok,
                             const float* __restrict__ pos,
                             const float* __restrict__ phase,
                             float* __restrict__ x) {
    int row = blockIdx.x;
    int l   = row % SEQL;
    int t   = idx[row];
    for (int d = threadIdx.x; d < DMODEL; d += blockDim.x) {
        float phi = tanhf(phase[d]) * 3.14159265358979323846f;
        float fac = cosf(phi) - sinf(phi);
        x[(long)row * DMODEL + d] =
            (tok[(long)t * DMODEL + d] + pos[(long)l * DMODEL + d]) * fac;
    }
}

// ---------------- LayerNorm (fp32 in, fp16 out; shuffle reduction) ----------
__global__ void ln_kernel(const float* __restrict__ x,
                          const float* __restrict__ w,
                          const float* __restrict__ b,
                          __half* __restrict__ o) {
    int row = blockIdx.x;
    const float* xr = x + (long)row * DMODEL;
    int tid = threadIdx.x;
    int wid = tid >> 5, lane = tid & 31;
    float s = 0.f, s2 = 0.f;
    float v[4];
#pragma unroll
    for (int j = 0; j < 4; j++) {
        v[j] = xr[tid + 256 * j];
        s += v[j]; s2 += v[j] * v[j];
    }
#pragma unroll
    for (int off = 16; off > 0; off >>= 1) {
        s  += __shfl_xor_sync(0xffffffffu, s,  off);
        s2 += __shfl_xor_sync(0xffffffffu, s2, off);
    }
    __shared__ float ps[8], ps2[8];
    if (lane == 0) { ps[wid] = s; ps2[wid] = s2; }
    __syncthreads();
    s  = ps[0] + ps[1] + ps[2] + ps[3] + ps[4] + ps[5] + ps[6] + ps[7];
    s2 = ps2[0] + ps2[1] + ps2[2] + ps2[3] + ps2[4] + ps2[5] + ps2[6] + ps2[7];
    float mean = s * (1.0f / DMODEL);
    float var  = s2 * (1.0f / DMODEL) - mean * mean;
    float rstd = rsqrtf(var + 1e-5f);
    __half* orow = o + (long)row * DMODEL;
#pragma unroll
    for (int j = 0; j < 4; j++) {
        int d = tid + 256 * j;
        orow[d] = __float2half_rn((v[j] - mean) * rstd * w[d] + b[d]);
    }
}

// ---------------- Fused flash attention (double-buffered K/V pipeline) ------
// grid: (8 q-tiles, 32 batch-heads), 256 threads (8 warps x 16 q-rows).
// V^T fragments via ldmatrix.trans; K/V loads for kt+1 prefetched during kt.
static constexpr int FA_KVB    = 128 * 72;                 // halves per buffer
static constexpr int FA_K_OFF  = 0;                        // Kt[2][FA_KVB]
static constexpr int FA_V_OFF  = 2 * FA_KVB;               // Vraw[2][FA_KVB]
static constexpr int FA_P_OFF  = 4 * FA_KVB;
static constexpr int FA_HALVES = FA_P_OFF + 128 * 136;
static constexpr int FA_SMEM   = FA_HALVES * 2;            // 108544 B

__global__ __launch_bounds__(256)
void flash_attn_kernel(const __half* __restrict__ qkv, __half* __restrict__ o) {
    extern __shared__ __half fh[];
    __half* Kt   = fh + FA_K_OFF;
    __half* Vraw = fh + FA_V_OFF;
    __half* Pu   = fh + FA_P_OFF;
    __half* Qs   = Pu;                     // Q staging reuses P region

    const int qt = blockIdx.x;
    const int bh = blockIdx.y;
    const int b  = bh >> 4;
    const int h  = bh & 15;

    const int tid  = threadIdx.x;
    const int wid  = tid >> 5;
    const int lane = tid & 31;
    const int g = lane >> 2, tig = lane & 3;

    const int lrow  = lane & 7;
    const int a_row = ((lane >> 3) & 1) * 8;
    const int a_k   = (lane >> 4) * 8;
    const int b_row = (lane >> 4) * 8;
    const int b_k   = ((lane >> 3) & 1) * 8;

    const __half* base = qkv + ((long)b * SEQL) * (3 * DMODEL) + h * HEADDIM;

    // ---- stage Q tile
    {
        int r = tid >> 1, hp = tid & 1;
        const __half* src = base + (long)(qt * 128 + r) * (3 * DMODEL) + hp * 32;
        uint32_t dst = smem_u32(&Qs[r * 72 + hp * 32]);
#pragma unroll
        for (int i = 0; i < 4; i++) cp16(dst + i * 16, src + i * 8);
    }
    CP_COMMIT(); CP_WAIT0(); __syncthreads();

    const __half2 qscale = __floats2half2_rn(0.125f, 0.125f);
    uint32_t qf[4][4];
    {
        uint32_t qbase = smem_u32(Qs) +
            ((wid * 16 + a_row + lrow) * 72 + a_k) * 2;
#pragma unroll
        for (int ks = 0; ks < 4; ks++) {
            uint32_t r[4];
            ldsm_x4(r, qbase + ks * 32);
#pragma unroll
            for (int z = 0; z < 4; z++) {
                __half2 hv = __hmul2(*(__half2*)&r[z], qscale);
                qf[ks][z] = *(uint32_t*)&hv;
            }
        }
    }
    __syncthreads();

    float mold0 = -INFINITY, mold1 = -INFINITY;
    float l0 = 0.f, l1 = 0.f;
    float oacc[8][4];
#pragma unroll
    for (int n = 0; n < 8; n++)
#pragma unroll
        for (int r = 0; r < 4; r++) oacc[n][r] = 0.f;

    const uint32_t kt_b_base0 = smem_u32(Kt) + ((b_row + lrow) * 72 + b_k) * 2;
    const uint32_t v_bt_base0 = smem_u32(Vraw) + ((b_k + lrow) * 72 + b_row) * 2;
    const uint32_t pu_a_base = smem_u32(Pu) +
        ((wid * 16 + a_row + lrow) * 136 + a_k) * 2;
    constexpr uint32_t KVBUF = FA_KVB * 2;     // bytes per buffer

    auto kv_load = [&](int kt, int buf) {
        int r = tid >> 1, hp = tid & 1;
        const __half* ksrc = base + (long)(kt * 128 + r) * (3 * DMODEL) + DMODEL + hp * 32;
        const __half* vsrc = base + (long)(kt * 128 + r) * (3 * DMODEL) + 2 * DMODEL + hp * 32;
        uint32_t kd = smem_u32(&Kt[buf * FA_KVB + r * 72 + hp * 32]);
        uint32_t vd = smem_u32(&Vraw[buf * FA_KVB + r * 72 + hp * 32]);
#pragma unroll
        for (int i = 0; i < 4; i++) cp16(kd + i * 16, ksrc + i * 8);
#pragma unroll
        for (int i = 0; i < 4; i++) cp16(vd + i * 16, vsrc + i * 8);
    };

    kv_load(0, 0);
    CP_COMMIT();

    for (int kt = 0; kt <= qt; kt++) {
        const int buf = kt & 1;
        if (kt < qt) {
            kv_load(kt + 1, buf ^ 1);
            CP_COMMIT();
            CP_WAIT1();
        } else {
            CP_WAIT0();
        }
        __syncthreads();

        const uint32_t kt_b_base = kt_b_base0 + buf * KVBUF;
        const uint32_t v_bt_base = v_bt_base0 + buf * KVBUF;

        float sacc[16][4];
#pragma unroll
        for (int n = 0; n < 16; n++)
#pragma unroll
            for (int r = 0; r < 4; r++) sacc[n][r] = 0.f;
#pragma unroll
        for (int ntp = 0; ntp < 8; ntp++) {
            uint32_t baddr = kt_b_base + ntp * (16 * 72 * 2);
#pragma unroll
            for (int ks = 0; ks < 4; ks++) {
                uint32_t r[4];
                ldsm_x4(r, baddr + ks * 32);
                mma_f16(sacc[2 * ntp    ], qf[ks], r);
                mma_f16(sacc[2 * ntp + 1], qf[ks], r + 2);
            }
        }

        if (kt == qt) {
            int r0 = wid * 16 + g, r1 = r0 + 8;
#pragma unroll
            for (int nt = 0; nt < 16; nt++) {
                int c0 = nt * 8 + tig * 2;
                if (c0     > r0) sacc[nt][0] = -INFINITY;
                if (c0 + 1 > r0) sacc[nt][1] = -INFINITY;
                if (c0     > r1) sacc[nt][2] = -INFINITY;
                if (c0 + 1 > r1) sacc[nt][3] = -INFINITY;
            }
        }

        float tm0 = -INFINITY, tm1 = -INFINITY;
#pragma unroll
        for (int nt = 0; nt < 16; nt++) {
            tm0 = fmaxf(tm0, fmaxf(sacc[nt][0], sacc[nt][1]));
            tm1 = fmaxf(tm1, fmaxf(sacc[nt][2], sacc[nt][3]));
        }
        tm0 = fmaxf(tm0, __shfl_xor_sync(0xffffffffu, tm0, 1));
        tm0 = fmaxf(tm0, __shfl_xor_sync(0xffffffffu, tm0, 2));
        tm1 = fmaxf(tm1, __shfl_xor_sync(0xffffffffu, tm1, 1));
        tm1 = fmaxf(tm1, __shfl_xor_sync(0xffffffffu, tm1, 2));
        float mn0 = fmaxf(mold0, tm0), mn1 = fmaxf(mold1, tm1);
        float a0 = __expf(mold0 - mn0), a1 = __expf(mold1 - mn1);

        float sum0 = 0.f, sum1 = 0.f;
        int prow = wid * 16 + g;
        uint32_t* Pw = (uint32_t*)Pu;
#pragma unroll
        for (int nt = 0; nt < 16; nt++) {
            float p0 = __expf(sacc[nt][0] - mn0);
            float p1 = __expf(sacc[nt][1] - mn0);
            float p2 = __expf(sacc[nt][2] - mn1);
            float p3 = __expf(sacc[nt][3] - mn1);
            sum0 += p0 + p1; sum1 += p2 + p3;
            int c = nt * 4 + tig;
            Pw[(prow    ) * 68 + c] = pack_h2(p0, p1);
            Pw[(prow + 8) * 68 + c] = pack_h2(p2, p3);
        }
        sum0 += __shfl_xor_sync(0xffffffffu, sum0, 1);
        sum0 += __shfl_xor_sync(0xffffffffu, sum0, 2);
        sum1 += __shfl_xor_sync(0xffffffffu, sum1, 1);
        sum1 += __shfl_xor_sync(0xffffffffu, sum1, 2);
        l0 = l0 * a0 + sum0;
        l1 = l1 * a1 + sum1;
#pragma unroll
        for (int nt = 0; nt < 8; nt++) {
            oacc[nt][0] *= a0; oacc[nt][1] *= a0;
            oacc[nt][2] *= a1; oacc[nt][3] *= a1;
        }
        mold0 = mn0; mold1 = mn1;
        __syncthreads();

        // ---- O += P @ V  (A from Pu; B = V^T tiles via ldmatrix.trans)
#pragma unroll
        for (int ks = 0; ks < 8; ks++) {
            uint32_t af[4];
            ldsm_x4(af, pu_a_base + ks * 32);
            uint32_t vb = v_bt_base + ks * (16 * 72 * 2);
#pragma unroll
            for (int ntp = 0; ntp < 4; ntp++) {
                uint32_t r[4];
                ldsm_x4_t(r, vb + ntp * 32);
                mma_f16(oacc[2 * ntp    ], af, r);
                mma_f16(oacc[2 * ntp + 1], af, r + 2);
            }
        }
        __syncthreads();   // Pu + this buf fully consumed before reuse
    }

    float i0 = 1.0f / l0, i1 = 1.0f / l1;
    int tok = b * SEQL + qt * 128 + wid * 16 + g;
    __half* o0 = o + (long)tok * DMODEL + h * HEADDIM;
    __half* o1 = o0 + 8 * DMODEL;
#pragma unroll
    for (int nt = 0; nt < 8; nt++) {
        int c = nt * 8 + tig * 2;
        *(uint32_t*)&o0[c] = pack_h2(oacc[nt][0] * i0, oacc[nt][1] * i0);
        *(uint32_t*)&o1[c] = pack_h2(oacc[nt][2] * i1, oacc[nt][3] * i1);
    }
}

// ---------------- fp16 mma.sync GEMM (2-stage + ldmatrix, BK=64) ------------
// C[m,n] = sum_k A[m*lda+k] * B[n*sBn+k]  (+bias)(gelu); out fp32(+res) or fp16
// flags: 1 = gelu, 16 = grid swap, 32 = fp16 output
// BM=128, BN=128, BK=64 halves; 8 warps 2x4; warp tile 64x32.
__global__ __launch_bounds__(256)
void mma_gemm(const __half* __restrict__ A, int lda,
              const __half* __restrict__ Bp, long sBn,
              const float* __restrict__ bias,
              const float* __restrict__ res, int ldr,
              void* __restrict__ Cv, int ldc,
              int K, int flags) {
    constexpr int BM = 128, BN = 128, BK = 64, LDSH = BK + 8;   // 72 halves/row
    extern __shared__ __half smh[];
    __half* As = smh;                         // [2][BM][72]
    __half* Bs = smh + 2 * BM * LDSH;         // [2][BN][72]

    int bx = blockIdx.x, by = blockIdx.y;
    if (flags & 16) { int t = bx; bx = by; by = t; }
    const int bm0 = by * BM;
    const int bn0 = bx * BN;
    const int T = K / BK;

    const int tid  = threadIdx.x;
    const int w    = tid >> 5;
    const int lane = tid & 31;
    const int wm = w >> 2, wn = w & 3;
    const int g = lane >> 2, tig = lane & 3;

    const int lrow  = lane & 7;
    const int a_row = ((lane >> 3) & 1) * 8;
    const int a_k   = (lane >> 4) * 8;
    const int b_row = (lane >> 4) * 8;
    const int b_k   = ((lane >> 3) & 1) * 8;

    const uint32_t a_base = smem_u32(As) +
        ((wm * 64 + a_row + lrow) * LDSH + a_k) * 2;
    const uint32_t b_base = smem_u32(Bs) +
        ((wn * 32 + b_row + lrow) * LDSH + b_k) * 2;
    constexpr uint32_t ABUF = BM * LDSH * 2;
    constexpr uint32_t BBUF = BN * LDSH * 2;

    float acc[4][4][4];
#pragma unroll
    for (int i = 0; i < 4; i++)
#pragma unroll
        for (int j = 0; j < 4; j++)
#pragma unroll
            for (int r = 0; r < 4; r++) acc[i][j][r] = 0.0f;

    auto load_tile = [&](int it, int buf) {
        const int k0 = it * BK;
#pragma unroll
        for (int t = 0; t < 4; t++) {
            int vv = tid + t * 256;
            int m = vv >> 3, c = vv & 7;
            cp16(smem_u32(&As[(buf * BM + m) * LDSH + c * 8]),
                 A + (long)(bm0 + m) * lda + k0 + c * 8);
        }
#pragma unroll
        for (int t = 0; t < 4; t++) {
            int vv = tid + t * 256;
            int n = vv >> 3, c = vv & 7;
            cp16(smem_u32(&Bs[(buf * BN + n) * LDSH + c * 8]),
                 Bp + (long)(bn0 + n) * sBn + k0 + c * 8);
        }
    };

    load_tile(0, 0);
    CP_COMMIT();

    for (int it = 0; it < T; it++) {
        const int buf = it & 1;
        if (it + 1 < T) {
            load_tile(it + 1, buf ^ 1);
            CP_COMMIT();
            CP_WAIT1();
        } else {
            CP_WAIT0();
        }
        __syncthreads();

        const uint32_t ab = a_base + buf * ABUF;
        const uint32_t bb = b_base + buf * BBUF;

#pragma unroll
        for (int ks = 0; ks < 4; ks++) {       // 4 k16-steps per BK=64
            uint32_t af[4][4];
#pragma unroll
            for (int i = 0; i < 4; i++)
                ldsm_x4(af[i], ab + i * (16 * LDSH * 2) + ks * 32);
            uint32_t bf[4][4];                  // 2 ldmatrix cover 4 n8 tiles
            ldsm_x4(bf[0], bb + ks * 32);
            ldsm_x4(bf[2], bb + 16 * LDSH * 2 + ks * 32);
#pragma unroll
            for (int i = 0; i < 4; i++) {
                mma_f16(acc[i][0], af[i], bf[0]);
                mma_f16(acc[i][1], af[i], bf[0] + 2);
                mma_f16(acc[i][2], af[i], bf[2]);
                mma_f16(acc[i][3], af[i], bf[2] + 2);
            }
        }
        __syncthreads();
    }

    // epilogue -----------------------------------------------------------
#pragma unroll
    for (int i = 0; i < 4; i++) {
        int r0 = bm0 + wm * 64 + i * 16 + g;
#pragma unroll
        for (int j = 0; j < 4; j++) {
            int c = bn0 + wn * 32 + j * 8 + tig * 2;
            float e00 = acc[i][j][0], e01 = acc[i][j][1];
            float e10 = acc[i][j][2], e11 = acc[i][j][3];
            if (bias) {
                float2 bb2 = *reinterpret_cast<const float2*>(bias + c);
                e00 += bb2.x; e01 += bb2.y; e10 += bb2.x; e11 += bb2.y;
            }
            if (flags & 1) {
                e00 = gelu_exact(e00); e01 = gelu_exact(e01);
                e10 = gelu_exact(e10); e11 = gelu_exact(e11);
            }
            if (flags & 32) {
                __half* C = (__half*)Cv;
                *(uint32_t*)&C[(long)r0 * ldc + c]       = pack_h2(e00, e01);
                *(uint32_t*)&C[(long)(r0 + 8) * ldc + c] = pack_h2(e10, e11);
            } else {
                float* C = (float*)Cv;
                if (res) {
                    float2 ra = *reinterpret_cast<const float2*>(
                        res + (long)r0 * ldr + c);
                    float2 rb = *reinterpret_cast<const float2*>(
                        res + (long)(r0 + 8) * ldr + c);
                    e00 += ra.x; e01 += ra.y; e10 += rb.x; e11 += rb.y;
                }
                *reinterpret_cast<float2*>(C + (long)r0 * ldc + c) =
                    make_float2(e00, e01);
                *reinterpret_cast<float2*>(C + (long)(r0 + 8) * ldc + c) =
                    make_float2(e10, e11);
            }
        }
    }
}

// ---------------- host-side launch helper ----------------
static constexpr int GEMM_SMEM = (2 * 128 * 72 + 2 * 128 * 72) * 2;  // 73728

static void tgemm(const __half* A, int lda, const __half* B, long sBn,
                  const float* bias, const float* res, int ldr,
                  void* C, int ldc, int M, int N, int K, int flags) {
    dim3 gdim;
    if (flags & 16) gdim = dim3(M / 128, N / 128, 1);
    else            gdim = dim3(N / 128, M / 128, 1);
    mma_gemm<<<gdim, 256, GEMM_SMEM>>>(A, lda, B, sBn, bias, res, ldr,
                                       C, ldc, K, flags);
}

// ---------------- entry point ----------------
extern "C" void kernel_launch(void* const* d_in, const int* in_sizes, int n_in,
                              void* d_out, int out_size) {
    const int*   idx   = (const int*)  d_in[0];
    const float* tok   = (const float*)d_in[1];
    const float* pos   = (const float*)d_in[2];
    const float* phase = (const float*)d_in[3];
    const float* ln1w  = (const float*)d_in[4];
    const float* ln1b  = (const float*)d_in[5];

    const float *ln2w, *ln2b;
    int wbase;
    if (in_sizes[6] == DEPTH * DMODEL) {        // dict order
        ln2w = (const float*)d_in[6];
        ln2b = (const float*)d_in[7];
        wbase = 8;
    } else {                                     // signature order fallback
        ln2w = (const float*)d_in[22];
        ln2b = (const float*)d_in[23];
        wbase = 6;
    }
    const float* Wq = (const float*)d_in[wbase + 0];
    const float* bq = (const float*)d_in[wbase + 1];
    const float* Bq = (const float*)d_in[wbase + 2];
    const float* Aq = (const float*)d_in[wbase + 3];
    const float* Wk = (const float*)d_in[wbase + 4];
    const float* bk = (const float*)d_in[wbase + 5];
    const float* Bk = (const float*)d_in[wbase + 6];
    const float* Ak = (const float*)d_in[wbase + 7];
    const float* Wv = (const float*)d_in[wbase + 8];
    const float* bv = (const float*)d_in[wbase + 9];
    const float* Bv = (const float*)d_in[wbase + 10];
    const float* Av = (const float*)d_in[wbase + 11];
    const float* Wo = (const float*)d_in[wbase + 12];
    const float* bo = (const float*)d_in[wbase + 13];
    const float* Bo = (const float*)d_in[wbase + 14];
    const float* Ao = (const float*)d_in[wbase + 15];
    const float* W1 = (const float*)d_in[24];
    const float* b1 = (const float*)d_in[25];
    const float* W2 = (const float*)d_in[26];
    const float* b2 = (const float*)d_in[27];
    const float* lnfw = (const float*)d_in[28];
    const float* lnfb = (const float*)d_in[29];
    const float* headW = (const float*)d_in[30];
    float* out = (float*)d_out;

    float *x, *bqkv;
    __half *h, *qkv, *o, *ff, *wqkv, *wo, *w1c, *w2c, *headc;
    cudaGetSymbolAddress((void**)&x,    g_x);
    cudaGetSymbolAddress((void**)&h,    g_h);
    cudaGetSymbolAddress((void**)&qkv,  g_qkv);
    cudaGetSymbolAddress((void**)&o,    g_o);
    cudaGetSymbolAddress((void**)&ff,   g_ff);
    cudaGetSymbolAddress((void**)&wqkv, g_wqkv);
    cudaGetSymbolAddress((void**)&bqkv, g_bqkv);
    cudaGetSymbolAddress((void**)&wo,   g_wo);
    cudaGetSymbolAddress((void**)&w1c,  g_w1c);
    cudaGetSymbolAddress((void**)&w2c,  g_w2c);
    cudaGetSymbolAddress((void**)&headc, g_headc);

    cudaFuncSetAttribute(flash_attn_kernel,
                         cudaFuncAttributeMaxDynamicSharedMemorySize, FA_SMEM);
    cudaFuncSetAttribute(mma_gemm,
                         cudaFuncAttributeMaxDynamicSharedMemorySize, GEMM_SMEM);

    const int D = DMODEL;
    const long DD = (long)D * D;

    // 1) weight prep: LoRA folds + fp16 conversions
    {
        int nblk = (int)(DEPTH * DD / 4 / 256);
        weff_qkv_kernel<<<3 * nblk, 256>>>(Wq, Aq, Bq, Wk, Ak, Bk, Wv, Av, Bv,
                                           wqkv);
        weff_kernel<<<nblk, 256>>>(Wo, Ao, Bo, wo, DD, 0);
        bias_concat_kernel<<<DEPTH * 3 * D / 256, 256>>>(bq, bk, bv, bqkv);
        conv_f16_kernel<<<DEPTH * HIDDEN * D / 1024, 256>>>(W1, w1c);
        conv_f16_kernel<<<DEPTH * HIDDEN * D / 1024, 256>>>(W2, w2c);
        conv_f16_kernel<<<VOCAB * D / 1024, 256>>>(headW, headc);
    }
    embed_kernel<<<NTOK, 256>>>(idx, tok, pos, phase, x);

    // 2) transformer layers
    for (int i = 0; i < DEPTH; i++) {
        const __half* wqkv_i = wqkv + (long)i * 3 * DD;
        const __half* woi    = wo + (long)i * DD;

        ln_kernel<<<NTOK, 256>>>(x, ln1w + i * D, ln1b + i * D, h);

        // fused QKV (fp16 output)
        tgemm(h, D, wqkv_i, D, bqkv + (long)i * 3 * D, nullptr, 0,
              qkv, 3 * D, NTOK, 3 * D, D, /*flags=*/32);

        flash_attn_kernel<<<dim3(SEQL / 128, BATCH * NHEAD), 256, FA_SMEM>>>(
            qkv, o);

        // x = x + o @ Wo_eff^T + bo  (fp32 output + residual)
        tgemm(o, D, woi, D, bo + i * D, x, D, x, D, NTOK, D, D, 0);

        ln_kernel<<<NTOK, 256>>>(x, ln2w + i * D, ln2b + i * D, h);

        // ff = fp16(gelu(h @ W1^T + b1))
        tgemm(h, D, w1c + (long)i * HIDDEN * D, D, b1 + i * HIDDEN,
              nullptr, 0, ff, HIDDEN, NTOK, HIDDEN, D, /*flags=*/1 | 32);
        // x = x + ff @ W2^T + b2
        tgemm(ff, HIDDEN, w2c + (long)i * D * HIDDEN, HIDDEN, b2 + i * D,
              x, D, x, D, NTOK, D, HIDDEN, 0);
    }

    // 3) final LN + LM head (grid-swapped for L2 B reuse)
    ln_kernel<<<NTOK, 256>>>(x, lnfw, lnfb, h);
    tgemm(h, D, headc, D, nullptr, nullptr, 0, out, VOCAB,
          NTOK, VOCAB, D, /*flags=*/16);
}